// round 13
// baseline (speedup 1.0000x reference)
#include <cuda_runtime.h>
#include <cuda_fp16.h>
#include <cuda_bf16.h>
#include <cstdint>
#include <type_traits>

// ---------------------------------------------------------------------------
// CausalAttention (random-feature attention) — mma.sync 3-term split GEMMs
// (zero-C drain-group starts, RN drain every 2 k-chunks on all GEMMs)
// + d-split x2, 8-timesteps-per-iteration causal scan (R6 2-sync skeleton).
// ---------------------------------------------------------------------------

#define T_DIM 2048
#define B_DIM 8
#define E_DIM 1024
#define H_DIM 16
#define TB    (T_DIM * B_DIM)          // 16384 rows
#define EPS_RFA 1e-6f

#define BM 128
#define BN 128
#define BK 32
#define NKT (E_DIM / BK)                // 32
#define ROW_B 80
#define ARR_B (128 * ROW_B)
#define STAGE_B (4 * ARR_B)             // 40960
#define NSTAGE 4
#define SM_BIAS 0
#define SM_STAGE0 1024
#define SM_TOTAL (SM_STAGE0 + NSTAGE * STAGE_B)   // 164864

#define SCAN_NS 8                       // timesteps per scan iteration

// ------------------------- scratch (static device) -------------------------
__device__ __half g_x_hi[TB * E_DIM];
__device__ __half g_x_lo[TB * E_DIM];
__device__ __half g_Wq_hi[E_DIM * E_DIM];
__device__ __half g_Wq_lo[E_DIM * E_DIM];
__device__ __half g_Wk_hi[E_DIM * E_DIM];
__device__ __half g_Wk_lo[E_DIM * E_DIM];
__device__ __half g_Wv_hi[E_DIM * E_DIM];
__device__ __half g_Wv_lo[E_DIM * E_DIM];
__device__ __nv_bfloat16 g_Wo_hi[E_DIM * E_DIM];
__device__ __nv_bfloat16 g_Wo_lo[E_DIM * E_DIM];
__device__ float g_bq_eff[E_DIM];
__device__ float g_bk_eff[E_DIM];
__device__ float g_v   [TB * E_DIM];
__device__ float g_phiq[(size_t)TB * 2048];
__device__ float g_phik[(size_t)TB * 2048];
__device__ __nv_bfloat16 g_attn_hi[TB * E_DIM];
__device__ __nv_bfloat16 g_attn_lo[TB * E_DIM];

// ----------------------------- PTX helpers ---------------------------------
__device__ __forceinline__ uint32_t smem_to_u32(const void* p) {
    uint32_t a;
    asm("{ .reg .u64 t; cvta.to.shared.u64 t, %1; cvt.u32.u64 %0, t; }" : "=r"(a) : "l"(p));
    return a;
}
__device__ __forceinline__ void cp16(uint32_t dst, const void* src) {
    asm volatile("cp.async.cg.shared.global [%0], [%1], 16;" :: "r"(dst), "l"(src) : "memory");
}
#define CP_COMMIT() asm volatile("cp.async.commit_group;" ::: "memory")
#define CP_WAIT2()  asm volatile("cp.async.wait_group 2;" ::: "memory")

__device__ __forceinline__ void ldsm4(uint32_t* r, uint32_t addr) {
    asm volatile("ldmatrix.sync.aligned.m8n8.x4.shared.b16 {%0,%1,%2,%3}, [%4];"
                 : "=r"(r[0]), "=r"(r[1]), "=r"(r[2]), "=r"(r[3]) : "r"(addr));
}
// accumulate variants (d == c)
__device__ __forceinline__ void mma_f16(float* d, const uint32_t* a, const uint32_t* b) {
    asm volatile(
        "mma.sync.aligned.m16n8k16.row.col.f32.f16.f16.f32 "
        "{%0,%1,%2,%3}, {%4,%5,%6,%7}, {%8,%9}, {%0,%1,%2,%3};"
        : "+f"(d[0]), "+f"(d[1]), "+f"(d[2]), "+f"(d[3])
        : "r"(a[0]), "r"(a[1]), "r"(a[2]), "r"(a[3]), "r"(b[0]), "r"(b[1]));
}
__device__ __forceinline__ void mma_bf16(float* d, const uint32_t* a, const uint32_t* b) {
    asm volatile(
        "mma.sync.aligned.m16n8k16.row.col.f32.bf16.bf16.f32 "
        "{%0,%1,%2,%3}, {%4,%5,%6,%7}, {%8,%9}, {%0,%1,%2,%3};"
        : "+f"(d[0]), "+f"(d[1]), "+f"(d[2]), "+f"(d[3])
        : "r"(a[0]), "r"(a[1]), "r"(a[2]), "r"(a[3]), "r"(b[0]), "r"(b[1]));
}
// zero-C variants (d written fresh, c = 0) — first MMA of each drain group
__device__ __forceinline__ void mma_f16_zc(float* d, const uint32_t* a, const uint32_t* b) {
    asm volatile(
        "mma.sync.aligned.m16n8k16.row.col.f32.f16.f16.f32 "
        "{%0,%1,%2,%3}, {%4,%5,%6,%7}, {%8,%9}, {%10,%10,%10,%10};"
        : "=f"(d[0]), "=f"(d[1]), "=f"(d[2]), "=f"(d[3])
        : "r"(a[0]), "r"(a[1]), "r"(a[2]), "r"(a[3]), "r"(b[0]), "r"(b[1]),
          "f"(0.0f));
}
__device__ __forceinline__ void mma_bf16_zc(float* d, const uint32_t* a, const uint32_t* b) {
    asm volatile(
        "mma.sync.aligned.m16n8k16.row.col.f32.bf16.bf16.f32 "
        "{%0,%1,%2,%3}, {%4,%5,%6,%7}, {%8,%9}, {%10,%10,%10,%10};"
        : "=f"(d[0]), "=f"(d[1]), "=f"(d[2]), "=f"(d[3])
        : "r"(a[0]), "r"(a[1]), "r"(a[2]), "r"(a[3]), "r"(b[0]), "r"(b[1]),
          "f"(0.0f));
}

// ---------------------------------------------------------------------------
// fp32 -> fp16 hi/lo split (with pre-scale)
// ---------------------------------------------------------------------------
__global__ void __launch_bounds__(256) f32_to_f16hl(
    const float* __restrict__ in, __half* __restrict__ hi,
    __half* __restrict__ lo, int n, float scale)
{
    int i = (blockIdx.x * 256 + threadIdx.x) * 4;
    if (i >= n) return;
    float4 v = *(const float4*)(in + i);
    float a[4] = {v.x * scale, v.y * scale, v.z * scale, v.w * scale};
    __half h[4], l[4];
#pragma unroll
    for (int j = 0; j < 4; j++) {
        h[j] = __float2half_rn(a[j]);
        l[j] = __float2half_rn(a[j] - __half2float(h[j]));
    }
    *(__half2*)(hi + i)     = __halves2half2(h[0], h[1]);
    *(__half2*)(hi + i + 2) = __halves2half2(h[2], h[3]);
    *(__half2*)(lo + i)     = __halves2half2(l[0], l[1]);
    *(__half2*)(lo + i + 2) = __halves2half2(l[2], l[3]);
}

// fp32 -> bf16 hi/lo split
__global__ void __launch_bounds__(256) f32_to_bf16hl(
    const float* __restrict__ in, __nv_bfloat16* __restrict__ hi,
    __nv_bfloat16* __restrict__ lo, int n)
{
    int i = (blockIdx.x * 256 + threadIdx.x) * 4;
    if (i >= n) return;
    float4 v = *(const float4*)(in + i);
    float a[4] = {v.x, v.y, v.z, v.w};
    __nv_bfloat16 h[4], l[4];
#pragma unroll
    for (int j = 0; j < 4; j++) {
        h[j] = __float2bfloat16(a[j]);
        l[j] = __float2bfloat16(a[j] - __bfloat162float(h[j]));
    }
    *(__nv_bfloat162*)(hi + i)     = __halves2bfloat162(h[0], h[1]);
    *(__nv_bfloat162*)(hi + i + 2) = __halves2bfloat162(h[2], h[3]);
    *(__nv_bfloat162*)(lo + i)     = __halves2bfloat162(l[0], l[1]);
    *(__nv_bfloat162*)(lo + i + 2) = __halves2bfloat162(l[2], l[3]);
}

// ---------------------------------------------------------------------------
// Weight prep: Weff[h*64+k, e] = scale * sum_d rm[h,k,d] * W[h*64+d, e]
// matrix written as fp16 hi/lo with extra x64; beff fp32 (logical scale).
// ---------------------------------------------------------------------------
__global__ void __launch_bounds__(256) prep_weff(
    const float* __restrict__ rm, const float* __restrict__ W,
    const float* __restrict__ bvec, __half* __restrict__ Whi,
    __half* __restrict__ Wlo, float* __restrict__ beff, float scale)
{
    const int h  = blockIdx.y;
    const int e0 = blockIdx.x * 64;
    const int tid = threadIdx.x;

    __shared__ float rs[64][65];
    __shared__ float ws[64][65];

    for (int i = tid; i < 4096; i += 256) {
        int k = i >> 6, dd = i & 63;
        rs[k][dd] = rm[h * 4096 + i];
    }
    for (int i = tid; i < 4096; i += 256) {
        int dd = i >> 6, e = i & 63;
        ws[dd][e] = W[(size_t)(h * 64 + dd) * E_DIM + e0 + e];
    }
    __syncthreads();

    const int tk = (tid >> 4) * 4;
    const int te = (tid & 15) * 4;
    float acc[4][4];
#pragma unroll
    for (int i = 0; i < 4; i++)
#pragma unroll
        for (int j = 0; j < 4; j++) acc[i][j] = 0.f;

#pragma unroll 8
    for (int dd = 0; dd < 64; dd++) {
        float a0 = rs[tk + 0][dd], a1 = rs[tk + 1][dd];
        float a2 = rs[tk + 2][dd], a3 = rs[tk + 3][dd];
        float b0 = ws[dd][te + 0], b1 = ws[dd][te + 1];
        float b2 = ws[dd][te + 2], b3 = ws[dd][te + 3];
        acc[0][0] += a0 * b0; acc[0][1] += a0 * b1; acc[0][2] += a0 * b2; acc[0][3] += a0 * b3;
        acc[1][0] += a1 * b0; acc[1][1] += a1 * b1; acc[1][2] += a1 * b2; acc[1][3] += a1 * b3;
        acc[2][0] += a2 * b0; acc[2][1] += a2 * b1; acc[2][2] += a2 * b2; acc[2][3] += a2 * b3;
        acc[3][0] += a3 * b0; acc[3][1] += a3 * b1; acc[3][2] += a3 * b2; acc[3][3] += a3 * b3;
    }
#pragma unroll
    for (int i = 0; i < 4; i++)
#pragma unroll
        for (int j = 0; j < 4; j++) {
            float val = 64.f * scale * acc[i][j];
            size_t idx = (size_t)(h * 64 + tk + i) * E_DIM + e0 + te + j;
            __half hv = __float2half_rn(val);
            Whi[idx] = hv;
            Wlo[idx] = __float2half_rn(val - __half2float(hv));
        }

    if (blockIdx.x == 0 && tid < 64) {
        float s = 0.f;
        for (int dd = 0; dd < 64; dd++) s += rs[tid][dd] * bvec[h * 64 + dd];
        beff[h * 64 + tid] = scale * s;
    }
}

// ---------------------------------------------------------------------------
// one k-stage loader — 256 threads, 2 iterations (8 cp.async per thread)
// ---------------------------------------------------------------------------
template <typename ET>
__device__ __forceinline__ void load_stage(
    const ET* __restrict__ Ahi, const ET* __restrict__ Alo,
    const ET* __restrict__ Bhi, const ET* __restrict__ Blo,
    int m0, int n0, int kc0, uint32_t st, int tid)
{
#pragma unroll
    for (int i = 0; i < 2; i++) {
        const int idx = tid + 256 * i;
        const int row = idx >> 2;
        const int u = idx & 3;
        const uint32_t doff = row * ROW_B + u * 16;
        const size_t aoff = (size_t)(m0 + row) * E_DIM + kc0 + u * 8;
        const size_t boff = (size_t)(n0 + row) * E_DIM + kc0 + u * 8;
        cp16(st + doff,             Ahi + aoff);
        cp16(st + ARR_B + doff,     Alo + aoff);
        cp16(st + 2 * ARR_B + doff, Bhi + boff);
        cp16(st + 3 * ARR_B + doff, Blo + boff);
    }
}

// ---------------------------------------------------------------------------
// HMMA GEMM: C = escale * (A @ B^T) + bias, 3-term split.
// 256 threads, 8 warps, warp tile 32x64; zero-C drain-group starts;
// RN drain every 2 k-chunks (chain 12 — R7-measured rel_err 3.76e-4);
// 4-stage cp.async ring, prefetch distance 3, single sync per k-iter.
// MODE 0: C fp32, row stride 1024.   MODE 1: phi epilogue, row stride 2048.
// ---------------------------------------------------------------------------
template <int MODE, typename ET>
__global__ void __launch_bounds__(256, 1) tc_gemm(
    const ET* __restrict__ Ahi, const ET* __restrict__ Alo,
    const ET* __restrict__ Bhi, const ET* __restrict__ Blo,
    const float* __restrict__ bias, float* __restrict__ Cout, float escale)
{
    extern __shared__ char smem[];
    const uint32_t sbase = smem_to_u32(smem);
    const int tid = threadIdx.x;
    const int wid = tid >> 5;
    const int lane = tid & 31;
    const int m0 = blockIdx.y * BM;
    const int n0 = blockIdx.x * BN;

    float* bias_s = (float*)(smem + SM_BIAS);
    if (tid < 128) bias_s[tid] = bias[n0 + tid];

    const int wm = wid >> 1;     // 0..3 -> rows wm*32
    const int wn = wid & 1;      // 0..1 -> cols wn*64
    const int g = lane >> 3;
    const int r = lane & 7;

    // preload 3 of 4 stages
#pragma unroll
    for (int s = 0; s < 3; s++) {
        load_stage(Ahi, Alo, Bhi, Blo, m0, n0, s * BK,
                   sbase + SM_STAGE0 + s * STAGE_B, tid);
        CP_COMMIT();
    }

    float accm[2][8][4];
    float accw[2][8][4];
#pragma unroll
    for (int mt = 0; mt < 2; mt++)
#pragma unroll
        for (int j = 0; j < 8; j++)
#pragma unroll
            for (int c = 0; c < 4; c++) accm[mt][j][c] = 0.f;

    const uint32_t a_row_off = (uint32_t)((wm * 32 + (g & 1) * 8 + r) * ROW_B + (g >> 1) * 16);
    const uint32_t b_row_off = (uint32_t)((wn * 64 + (g >> 1) * 8 + r) * ROW_B + (g & 1) * 16);

#pragma unroll 1
    for (int kt = 0; kt < NKT; kt++) {
        CP_WAIT2();        // slot kt%4 ready
        __syncthreads();   // all warps done reading slot (kt+3)%4

        // refill slot (kt+3)%4 — 3 iterations ahead
        if (kt + 3 < NKT)
            load_stage(Ahi, Alo, Bhi, Blo, m0, n0, (kt + 3) * BK,
                       sbase + SM_STAGE0 + ((kt + 3) % NSTAGE) * STAGE_B, tid);
        CP_COMMIT();

        const uint32_t st = sbase + SM_STAGE0 + (kt % NSTAGE) * STAGE_B;
        const uint32_t sA[2] = { st, st + ARR_B };
        const uint32_t sB[2] = { st + 2 * ARR_B, st + 3 * ARR_B };
        // fresh accumulator every 2 chunks (HMMA chain length 12)
        const bool fresh = ((kt & 1) == 0);
        const bool drain = ((kt & 1) == 1);

#pragma unroll
        for (int ks = 0; ks < 2; ks++) {
            uint32_t afr[2][2][4];   // [mt][hl][4]
            uint32_t bfr[4][2][4];   // [jp][hl][4]
#pragma unroll
            for (int mt = 0; mt < 2; mt++)
#pragma unroll
                for (int hl = 0; hl < 2; hl++)
                    ldsm4(afr[mt][hl], sA[hl] + a_row_off + mt * (16 * ROW_B) + ks * 32);
#pragma unroll
            for (int jp = 0; jp < 4; jp++)
#pragma unroll
                for (int hl = 0; hl < 2; hl++)
                    ldsm4(bfr[jp][hl], sB[hl] + b_row_off + jp * (16 * ROW_B) + ks * 32);

#pragma unroll
            for (int t = 0; t < 3; t++) {
                const int pa = (t == 2) ? 1 : 0;   // hh, hl, lh
                const int pb = (t == 1) ? 1 : 0;
                const bool zc = fresh && ks == 0 && t == 0;
#pragma unroll
                for (int mt = 0; mt < 2; mt++)
#pragma unroll
                    for (int j = 0; j < 8; j++) {
                        const uint32_t* bj = &bfr[j >> 1][pb][(j & 1) * 2];
                        if (std::is_same<ET, __half>::value) {
                            if (zc) mma_f16_zc(accw[mt][j], afr[mt][pa], bj);
                            else    mma_f16(accw[mt][j], afr[mt][pa], bj);
                        } else {
                            if (zc) mma_bf16_zc(accw[mt][j], afr[mt][pa], bj);
                            else    mma_bf16(accw[mt][j], afr[mt][pa], bj);
                        }
                    }
            }
        }
        if (drain) {   // working -> master (IEEE-RN)
#pragma unroll
            for (int mt = 0; mt < 2; mt++)
#pragma unroll
                for (int j = 0; j < 8; j++)
#pragma unroll
                    for (int c = 0; c < 4; c++) accm[mt][j][c] += accw[mt][j][c];
        }
    }

    // ------------------------------ epilogue --------------------------------
    const int qr = lane >> 2;
    const int qc = (lane & 3) * 2;
#pragma unroll
    for (int mt = 0; mt < 2; mt++) {
        const int row0 = m0 + wm * 32 + mt * 16 + qr;
#pragma unroll
        for (int j = 0; j < 8; j++) {
            const int coll = wn * 64 + j * 8 + qc;
            const int col = n0 + coll;
            const float b0 = bias_s[coll], b1 = bias_s[coll + 1];
            if (MODE == 0) {
                float2 v0 = make_float2(accm[mt][j][0] * escale + b0,
                                        accm[mt][j][1] * escale + b1);
                float2 v1 = make_float2(accm[mt][j][2] * escale + b0,
                                        accm[mt][j][3] * escale + b1);
                *(float2*)(Cout + (size_t)row0 * E_DIM + col) = v0;
                *(float2*)(Cout + (size_t)(row0 + 8) * E_DIM + col) = v1;
            } else {
                const int h = col >> 6, k = col & 63;
                float s0, c0s, s1, c1s, s2, c2s, s3, c3s;
                __sincosf(accm[mt][j][0] * escale + b0, &s0, &c0s);
                __sincosf(accm[mt][j][1] * escale + b1, &s1, &c1s);
                __sincosf(accm[mt][j][2] * escale + b0, &s2, &c2s);
                __sincosf(accm[mt][j][3] * escale + b1, &s3, &c3s);
                float* p0 = Cout + (size_t)row0 * 2048 + h * 128 + k;
                float* p1 = Cout + (size_t)(row0 + 8) * 2048 + h * 128 + k;
                p0[0] = s0 * 0.125f; p0[1]  = s1 * 0.125f;
                p0[64] = c0s * 0.125f; p0[65] = c1s * 0.125f;
                p1[0] = s2 * 0.125f; p1[1]  = s3 * 0.125f;
                p1[64] = c2s * 0.125f; p1[65] = c3s * 0.125f;
            }
        }
    }
}

// ---------------------------------------------------------------------------
// Causal RFA scan, d-split x2, EIGHT timesteps per iteration.
// block bx = bh*2 + dh handles output dims d in [dh*32, dh*32+32).
// 256 threads: dl = tid&31, kg = tid>>5. Thread owns s[kg*16+j][dh*32+dl].
// R6-proven 2-sync skeleton, amortized over 8 steps. attn -> bf16 hi/lo.
// ---------------------------------------------------------------------------
__global__ void __launch_bounds__(256) rfa_scan(
    const float* __restrict__ phiq, const float* __restrict__ phik,
    const float* __restrict__ v, __nv_bfloat16* __restrict__ attn_hi,
    __nv_bfloat16* __restrict__ attn_lo)
{
    const int bx = blockIdx.x;       // bh*2 + dh
    const int dh = bx & 1;
    const int bh = bx >> 1;
    const int h = bh & 15;
    const int b = bh >> 4;
    const int tid = threadIdx.x;
    const int dl = tid & 31;
    const int kg = tid >> 5;         // 0..7

    __shared__ float s_pq[2][SCAN_NS][128], s_pk[2][SCAN_NS][128];
    __shared__ float s_v[2][SCAN_NS][32];
    __shared__ float s_z[128];
    __shared__ float s_red[SCAN_NS][256];   // [step][tid]
    __shared__ float s_qzp[SCAN_NS][4];     // [step][warp128]

    float s_loc[16];
#pragma unroll
    for (int j = 0; j < 16; j++) s_loc[j] = 0.f;
    if (tid < 128) s_z[tid] = 0.f;

    const size_t phi_stride = (size_t)B_DIM * 2048;
    const size_t v_stride   = (size_t)B_DIM * 1024;
    const float* pq_base = phiq + (size_t)b * 2048 + h * 128;
    const float* pk_base = phik + (size_t)b * 2048 + h * 128;
    const float* v_base  = v    + (size_t)b * 1024 + h * 64 + dh * 32;
    const size_t o_off   = (size_t)b * 1024 + h * 64 + dh * 32;

    // preload group 0 (t = 0..SCAN_NS-1)
    float ld_pq[SCAN_NS], ld_pk[SCAN_NS], ld_v[SCAN_NS];
#pragma unroll
    for (int s = 0; s < SCAN_NS; s++) { ld_pq[s] = 0.f; ld_pk[s] = 0.f; ld_v[s] = 0.f; }
    if (tid < 128) {
#pragma unroll
        for (int s = 0; s < SCAN_NS; s++) {
            ld_pq[s] = pq_base[(size_t)s * phi_stride + tid];
            ld_pk[s] = pk_base[(size_t)s * phi_stride + tid];
        }
    }
    if (tid < 32) {
#pragma unroll
        for (int s = 0; s < SCAN_NS; s++) ld_v[s] = v_base[(size_t)s * v_stride + tid];
    }
    int buf = 0;
    if (tid < 128) {
#pragma unroll
        for (int s = 0; s < SCAN_NS; s++) {
            s_pq[0][s][tid] = ld_pq[s];
            s_pk[0][s][tid] = ld_pk[s];
        }
    }
    if (tid < 32) {
#pragma unroll
        for (int s = 0; s < SCAN_NS; s++) s_v[0][s][tid] = ld_v[s];
    }
    __syncthreads();

    const int NGRP = T_DIM / SCAN_NS;   // 256
    for (int it = 0; it < NGRP; it++) {
        const size_t t0 = (size_t)(SCAN_NS * it);

        // prefetch group it+1 (gmem -> regs)
        if (it + 1 < NGRP) {
            if (tid < 128) {
#pragma unroll
                for (int s = 0; s < SCAN_NS; s++) {
                    ld_pq[s] = pq_base[(t0 + SCAN_NS + s) * phi_stride + tid];
                    ld_pk[s] = pk_base[(t0 + SCAN_NS + s) * phi_stride + tid];
                }
            }
            if (tid < 32) {
#pragma unroll
                for (int s = 0; s < SCAN_NS; s++)
                    ld_v[s] = v_base[(t0 + SCAN_NS + s) * v_stride + tid];
            }
        }

        // s updates + q.s partials for SCAN_NS steps (sequential in s)
        {
            float vd[SCAN_NS];
            const float *pkp[SCAN_NS], *pqp[SCAN_NS];
#pragma unroll
            for (int s = 0; s < SCAN_NS; s++) {
                vd[s] = s_v[buf][s][dl];
                pkp[s] = &s_pk[buf][s][kg * 16];
                pqp[s] = &s_pq[buf][s][kg * 16];
            }
            float acc[SCAN_NS][4];
#pragma unroll
            for (int s = 0; s < SCAN_NS; s++)
#pragma unroll
                for (int c = 0; c < 4; c++) acc[s][c] = 0.f;
#pragma unroll
            for (int j = 0; j < 16; j += 4) {
#pragma unroll
                for (int s = 0; s < SCAN_NS; s++) {
                    float4 kk = *(const float4*)(pkp[s] + j);
                    float4 qq = *(const float4*)(pqp[s] + j);
                    s_loc[j + 0] += kk.x * vd[s]; acc[s][0] += qq.x * s_loc[j + 0];
                    s_loc[j + 1] += kk.y * vd[s]; acc[s][1] += qq.y * s_loc[j + 1];
                    s_loc[j + 2] += kk.z * vd[s]; acc[s][2] += qq.z * s_loc[j + 2];
                    s_loc[j + 3] += kk.w * vd[s]; acc[s][3] += qq.w * s_loc[j + 3];
                }
            }
#pragma unroll
            for (int s = 0; s < SCAN_NS; s++)
                s_red[s][tid] = (acc[s][0] + acc[s][1]) + (acc[s][2] + acc[s][3]);
        }

        // z updates + qz partials for SCAN_NS steps (threads 0..127)
        {
            float qzp[SCAN_NS];
#pragma unroll
            for (int s = 0; s < SCAN_NS; s++) qzp[s] = 0.f;
            if (tid < 128) {
                float z = s_z[tid];
#pragma unroll
                for (int s = 0; s < SCAN_NS; s++) {
                    z += s_pk[buf][s][tid];
                    qzp[s] = s_pq[buf][s][tid] * z;
                }
                s_z[tid] = z;
            }
#pragma unroll
            for (int off = 16; off; off >>= 1) {
#pragma unroll
                for (int s = 0; s < SCAN_NS; s++)
                    qzp[s] += __shfl_xor_sync(0xffffffffu, qzp[s], off);
            }
            if (tid < 128 && (tid & 31) == 0) {
#pragma unroll
                for (int s = 0; s < SCAN_NS; s++) s_qzp[s][tid >> 5] = qzp[s];
            }
        }
        __syncthreads();

        // finalize + write attn[t0..t0+SCAN_NS-1] for this block's 32 d's
        if (tid < 32) {
#pragma unroll
            for (int stp = 0; stp < SCAN_NS; stp++) {
                const float* rd = s_red[stp];
                float qs = ((rd[dl] + rd[32 + dl]) + (rd[64 + dl] + rd[96 + dl])) +
                           ((rd[128 + dl] + rd[160 + dl]) + (rd[192 + dl] + rd[224 + dl]));
                float qz = (s_qzp[stp][0] + s_qzp[stp][1]) +
                           (s_qzp[stp][2] + s_qzp[stp][3]);
                qz = fmaxf(qz, EPS_RFA);
                float o = qs / qz;
                __nv_bfloat16 hv = __float2bfloat16(o);
                size_t idx = (t0 + stp) * v_stride + o_off + dl;
                attn_hi[idx] = hv;
                attn_lo[idx] = __float2bfloat16(o - __bfloat162float(hv));
            }
        }

        // stage prefetched group into the other buffer
        buf ^= 1;
        if (it + 1 < NGRP) {
            if (tid < 128) {
#pragma unroll
                for (int s = 0; s < SCAN_NS; s++) {
                    s_pq[buf][s][tid] = ld_pq[s];
                    s_pk[buf][s][tid] = ld_pk[s];
                }
            }
            if (tid < 32) {
#pragma unroll
                for (int s = 0; s < SCAN_NS; s++) s_v[buf][s][tid] = ld_v[s];
            }
        }
        __syncthreads();
    }
}

// ---------------------------------------------------------------------------
extern "C" void kernel_launch(void* const* d_in, const int* in_sizes, int n_in,
                              void* d_out, int out_size)
{
    const float* x  = (const float*)d_in[0];
    const float* rm = (const float*)d_in[1];
    const float* Wq = (const float*)d_in[2];
    const float* bq = (const float*)d_in[3];
    const float* Wk = (const float*)d_in[4];
    const float* bk = (const float*)d_in[5];
    const float* Wv = (const float*)d_in[6];
    const float* bv = (const float*)d_in[7];
    const float* Wo = (const float*)d_in[8];
    const float* bo = (const float*)d_in[9];
    float* out = (float*)d_out;

    __half *x_hi, *x_lo, *Wq_hi, *Wq_lo, *Wk_hi, *Wk_lo, *Wv_hi, *Wv_lo;
    __nv_bfloat16 *Wo_hi, *Wo_lo, *attn_hi, *attn_lo;
    float *bq_eff, *bk_eff, *vbuf, *phiq, *phik;
    cudaGetSymbolAddress((void**)&x_hi, g_x_hi);
    cudaGetSymbolAddress((void**)&x_lo, g_x_lo);
    cudaGetSymbolAddress((void**)&Wq_hi, g_Wq_hi);
    cudaGetSymbolAddress((void**)&Wq_lo, g_Wq_lo);
    cudaGetSymbolAddress((void**)&Wk_hi, g_Wk_hi);
    cudaGetSymbolAddress((void**)&Wk_lo, g_Wk_lo);
    cudaGetSymbolAddress((void**)&Wv_hi, g_Wv_hi);
    cudaGetSymbolAddress((void**)&Wv_lo, g_Wv_lo);
    cudaGetSymbolAddress((void**)&Wo_hi, g_Wo_hi);
    cudaGetSymbolAddress((void**)&Wo_lo, g_Wo_lo);
    cudaGetSymbolAddress((void**)&attn_hi, g_attn_hi);
    cudaGetSymbolAddress((void**)&attn_lo, g_attn_lo);
    cudaGetSymbolAddress((void**)&bq_eff, g_bq_eff);
    cudaGetSymbolAddress((void**)&bk_eff, g_bk_eff);
    cudaGetSymbolAddress((void**)&vbuf, g_v);
    cudaGetSymbolAddress((void**)&phiq, g_phiq);
    cudaGetSymbolAddress((void**)&phik, g_phik);

    cudaFuncSetAttribute((const void*)tc_gemm<0, __half>,
                         cudaFuncAttributeMaxDynamicSharedMemorySize, SM_TOTAL);
    cudaFuncSetAttribute((const void*)tc_gemm<1, __half>,
                         cudaFuncAttributeMaxDynamicSharedMemorySize, SM_TOTAL);
    cudaFuncSetAttribute((const void*)tc_gemm<0, __nv_bfloat16>,
                         cudaFuncAttributeMaxDynamicSharedMemorySize, SM_TOTAL);

    // conversions + weight prep: x scaled x256 (fp16 lo stays normal),
    // fp16 weights x64; bf16 Wo unscaled.
    f32_to_f16hl<<<TB * E_DIM / 1024, 256>>>(x, x_hi, x_lo, TB * E_DIM, 256.0f);
    prep_weff<<<dim3(16, 16), 256>>>(rm, Wq, bq, Wq_hi, Wq_lo, bq_eff, 0.125f);
    prep_weff<<<dim3(16, 16), 256>>>(rm, Wk, bk, Wk_hi, Wk_lo, bk_eff, 1.0f);
    f32_to_f16hl<<<E_DIM * E_DIM / 1024, 256>>>(Wv, Wv_hi, Wv_lo, E_DIM * E_DIM, 64.0f);
    f32_to_bf16hl<<<E_DIM * E_DIM / 1024, 256>>>(Wo, Wo_hi, Wo_lo, E_DIM * E_DIM);

    // tensor-core GEMMs (escale undoes x256 * x64)
    dim3 gg(E_DIM / BN, TB / BM);   // (8, 128)
    const float inv = 1.0f / 16384.0f;
    tc_gemm<1, __half><<<gg, 256, SM_TOTAL>>>(x_hi, x_lo, Wq_hi, Wq_lo, bq_eff, phiq, inv);
    tc_gemm<1, __half><<<gg, 256, SM_TOTAL>>>(x_hi, x_lo, Wk_hi, Wk_lo, bk_eff, phik, inv);
    tc_gemm<0, __half><<<gg, 256, SM_TOTAL>>>(x_hi, x_lo, Wv_hi, Wv_lo, bv, vbuf, inv);

    // causal scan, d-split x2, 8 timesteps/iter (256 blocks; attn bf16 split)
    rfa_scan<<<B_DIM * H_DIM * 2, 256>>>(phiq, phik, vbuf, attn_hi, attn_lo);

    // output projection (bf16 split, unamplified error path)
    tc_gemm<0, __nv_bfloat16><<<gg, 256, SM_TOTAL>>>(attn_hi, attn_lo, Wo_hi, Wo_lo, bo, out, 1.0f);
}

// round 14
// speedup vs baseline: 1.0373x; 1.0373x over previous
#include <cuda_runtime.h>
#include <cuda_fp16.h>
#include <cuda_bf16.h>
#include <cstdint>
#include <type_traits>

// ---------------------------------------------------------------------------
// CausalAttention (random-feature attention) — mma.sync split GEMMs.
// phi GEMMs: fp16 3-term, per-chunk RN drain (chain 6) — amplified path.
// v GEMM:    fp16 2-term (A*B_hi; drops x*Wv_lo ~ 2^-12 rel) — unamplified.
// out GEMM:  bf16 3-term (range-safe for attn spikes).
// Scan: d-split x2, 4 timesteps/iter, R6 2-sync skeleton.
// ---------------------------------------------------------------------------

#define T_DIM 2048
#define B_DIM 8
#define E_DIM 1024
#define H_DIM 16
#define TB    (T_DIM * B_DIM)          // 16384 rows
#define EPS_RFA 1e-6f

#define BM 128
#define BN 128
#define BK 32
#define NKT (E_DIM / BK)                // 32
#define ROW_B 80
#define ARR_B (128 * ROW_B)
#define STAGE_B (4 * ARR_B)             // 40960
#define NSTAGE 4
#define SM_BIAS 0
#define SM_STAGE0 1024
#define SM_TOTAL (SM_STAGE0 + NSTAGE * STAGE_B)   // 164864

#define SCAN_NS 4                       // timesteps per scan iteration

// ------------------------- scratch (static device) -------------------------
__device__ __half g_x_hi[TB * E_DIM];
__device__ __half g_x_lo[TB * E_DIM];
__device__ __half g_Wq_hi[E_DIM * E_DIM];
__device__ __half g_Wq_lo[E_DIM * E_DIM];
__device__ __half g_Wk_hi[E_DIM * E_DIM];
__device__ __half g_Wk_lo[E_DIM * E_DIM];
__device__ __half g_Wv_hi[E_DIM * E_DIM];
__device__ __half g_Wv_lo[E_DIM * E_DIM];
__device__ __nv_bfloat16 g_Wo_hi[E_DIM * E_DIM];
__device__ __nv_bfloat16 g_Wo_lo[E_DIM * E_DIM];
__device__ float g_bq_eff[E_DIM];
__device__ float g_bk_eff[E_DIM];
__device__ float g_v   [TB * E_DIM];
__device__ float g_phiq[(size_t)TB * 2048];
__device__ float g_phik[(size_t)TB * 2048];
__device__ __nv_bfloat16 g_attn_hi[TB * E_DIM];
__device__ __nv_bfloat16 g_attn_lo[TB * E_DIM];

// ----------------------------- PTX helpers ---------------------------------
__device__ __forceinline__ uint32_t smem_to_u32(const void* p) {
    uint32_t a;
    asm("{ .reg .u64 t; cvta.to.shared.u64 t, %1; cvt.u32.u64 %0, t; }" : "=r"(a) : "l"(p));
    return a;
}
__device__ __forceinline__ void cp16(uint32_t dst, const void* src) {
    asm volatile("cp.async.cg.shared.global [%0], [%1], 16;" :: "r"(dst), "l"(src) : "memory");
}
#define CP_COMMIT() asm volatile("cp.async.commit_group;" ::: "memory")
#define CP_WAIT2()  asm volatile("cp.async.wait_group 2;" ::: "memory")

__device__ __forceinline__ void ldsm4(uint32_t* r, uint32_t addr) {
    asm volatile("ldmatrix.sync.aligned.m8n8.x4.shared.b16 {%0,%1,%2,%3}, [%4];"
                 : "=r"(r[0]), "=r"(r[1]), "=r"(r[2]), "=r"(r[3]) : "r"(addr));
}
// accumulate variants (d == c)
__device__ __forceinline__ void mma_f16(float* d, const uint32_t* a, const uint32_t* b) {
    asm volatile(
        "mma.sync.aligned.m16n8k16.row.col.f32.f16.f16.f32 "
        "{%0,%1,%2,%3}, {%4,%5,%6,%7}, {%8,%9}, {%0,%1,%2,%3};"
        : "+f"(d[0]), "+f"(d[1]), "+f"(d[2]), "+f"(d[3])
        : "r"(a[0]), "r"(a[1]), "r"(a[2]), "r"(a[3]), "r"(b[0]), "r"(b[1]));
}
__device__ __forceinline__ void mma_bf16(float* d, const uint32_t* a, const uint32_t* b) {
    asm volatile(
        "mma.sync.aligned.m16n8k16.row.col.f32.bf16.bf16.f32 "
        "{%0,%1,%2,%3}, {%4,%5,%6,%7}, {%8,%9}, {%0,%1,%2,%3};"
        : "+f"(d[0]), "+f"(d[1]), "+f"(d[2]), "+f"(d[3])
        : "r"(a[0]), "r"(a[1]), "r"(a[2]), "r"(a[3]), "r"(b[0]), "r"(b[1]));
}
// zero-C variants (d written fresh, c = 0) — first MMA of each drain group
__device__ __forceinline__ void mma_f16_zc(float* d, const uint32_t* a, const uint32_t* b) {
    asm volatile(
        "mma.sync.aligned.m16n8k16.row.col.f32.f16.f16.f32 "
        "{%0,%1,%2,%3}, {%4,%5,%6,%7}, {%8,%9}, {%10,%10,%10,%10};"
        : "=f"(d[0]), "=f"(d[1]), "=f"(d[2]), "=f"(d[3])
        : "r"(a[0]), "r"(a[1]), "r"(a[2]), "r"(a[3]), "r"(b[0]), "r"(b[1]),
          "f"(0.0f));
}
__device__ __forceinline__ void mma_bf16_zc(float* d, const uint32_t* a, const uint32_t* b) {
    asm volatile(
        "mma.sync.aligned.m16n8k16.row.col.f32.bf16.bf16.f32 "
        "{%0,%1,%2,%3}, {%4,%5,%6,%7}, {%8,%9}, {%10,%10,%10,%10};"
        : "=f"(d[0]), "=f"(d[1]), "=f"(d[2]), "=f"(d[3])
        : "r"(a[0]), "r"(a[1]), "r"(a[2]), "r"(a[3]), "r"(b[0]), "r"(b[1]),
          "f"(0.0f));
}

// ---------------------------------------------------------------------------
// fp32 -> fp16 hi/lo split (with pre-scale)
// ---------------------------------------------------------------------------
__global__ void __launch_bounds__(256) f32_to_f16hl(
    const float* __restrict__ in, __half* __restrict__ hi,
    __half* __restrict__ lo, int n, float scale)
{
    int i = (blockIdx.x * 256 + threadIdx.x) * 4;
    if (i >= n) return;
    float4 v = *(const float4*)(in + i);
    float a[4] = {v.x * scale, v.y * scale, v.z * scale, v.w * scale};
    __half h[4], l[4];
#pragma unroll
    for (int j = 0; j < 4; j++) {
        h[j] = __float2half_rn(a[j]);
        l[j] = __float2half_rn(a[j] - __half2float(h[j]));
    }
    *(__half2*)(hi + i)     = __halves2half2(h[0], h[1]);
    *(__half2*)(hi + i + 2) = __halves2half2(h[2], h[3]);
    *(__half2*)(lo + i)     = __halves2half2(l[0], l[1]);
    *(__half2*)(lo + i + 2) = __halves2half2(l[2], l[3]);
}

// fp32 -> bf16 hi/lo split
__global__ void __launch_bounds__(256) f32_to_bf16hl(
    const float* __restrict__ in, __nv_bfloat16* __restrict__ hi,
    __nv_bfloat16* __restrict__ lo, int n)
{
    int i = (blockIdx.x * 256 + threadIdx.x) * 4;
    if (i >= n) return;
    float4 v = *(const float4*)(in + i);
    float a[4] = {v.x, v.y, v.z, v.w};
    __nv_bfloat16 h[4], l[4];
#pragma unroll
    for (int j = 0; j < 4; j++) {
        h[j] = __float2bfloat16(a[j]);
        l[j] = __float2bfloat16(a[j] - __bfloat162float(h[j]));
    }
    *(__nv_bfloat162*)(hi + i)     = __halves2bfloat162(h[0], h[1]);
    *(__nv_bfloat162*)(hi + i + 2) = __halves2bfloat162(h[2], h[3]);
    *(__nv_bfloat162*)(lo + i)     = __halves2bfloat162(l[0], l[1]);
    *(__nv_bfloat162*)(lo + i + 2) = __halves2bfloat162(l[2], l[3]);
}

// ---------------------------------------------------------------------------
// Weight prep: Weff[h*64+k, e] = scale * sum_d rm[h,k,d] * W[h*64+d, e]
// matrix written as fp16 hi/lo with extra x64; beff fp32 (logical scale).
// ---------------------------------------------------------------------------
__global__ void __launch_bounds__(256) prep_weff(
    const float* __restrict__ rm, const float* __restrict__ W,
    const float* __restrict__ bvec, __half* __restrict__ Whi,
    __half* __restrict__ Wlo, float* __restrict__ beff, float scale)
{
    const int h  = blockIdx.y;
    const int e0 = blockIdx.x * 64;
    const int tid = threadIdx.x;

    __shared__ float rs[64][65];
    __shared__ float ws[64][65];

    for (int i = tid; i < 4096; i += 256) {
        int k = i >> 6, dd = i & 63;
        rs[k][dd] = rm[h * 4096 + i];
    }
    for (int i = tid; i < 4096; i += 256) {
        int dd = i >> 6, e = i & 63;
        ws[dd][e] = W[(size_t)(h * 64 + dd) * E_DIM + e0 + e];
    }
    __syncthreads();

    const int tk = (tid >> 4) * 4;
    const int te = (tid & 15) * 4;
    float acc[4][4];
#pragma unroll
    for (int i = 0; i < 4; i++)
#pragma unroll
        for (int j = 0; j < 4; j++) acc[i][j] = 0.f;

#pragma unroll 8
    for (int dd = 0; dd < 64; dd++) {
        float a0 = rs[tk + 0][dd], a1 = rs[tk + 1][dd];
        float a2 = rs[tk + 2][dd], a3 = rs[tk + 3][dd];
        float b0 = ws[dd][te + 0], b1 = ws[dd][te + 1];
        float b2 = ws[dd][te + 2], b3 = ws[dd][te + 3];
        acc[0][0] += a0 * b0; acc[0][1] += a0 * b1; acc[0][2] += a0 * b2; acc[0][3] += a0 * b3;
        acc[1][0] += a1 * b0; acc[1][1] += a1 * b1; acc[1][2] += a1 * b2; acc[1][3] += a1 * b3;
        acc[2][0] += a2 * b0; acc[2][1] += a2 * b1; acc[2][2] += a2 * b2; acc[2][3] += a2 * b3;
        acc[3][0] += a3 * b0; acc[3][1] += a3 * b1; acc[3][2] += a3 * b2; acc[3][3] += a3 * b3;
    }
#pragma unroll
    for (int i = 0; i < 4; i++)
#pragma unroll
        for (int j = 0; j < 4; j++) {
            float val = 64.f * scale * acc[i][j];
            size_t idx = (size_t)(h * 64 + tk + i) * E_DIM + e0 + te + j;
            __half hv = __float2half_rn(val);
            Whi[idx] = hv;
            Wlo[idx] = __float2half_rn(val - __half2float(hv));
        }

    if (blockIdx.x == 0 && tid < 64) {
        float s = 0.f;
        for (int dd = 0; dd < 64; dd++) s += rs[tid][dd] * bvec[h * 64 + dd];
        beff[h * 64 + tid] = scale * s;
    }
}

// ---------------------------------------------------------------------------
// one k-stage loader — 256 threads, 2 iterations (8 cp.async per thread)
// ---------------------------------------------------------------------------
template <typename ET>
__device__ __forceinline__ void load_stage(
    const ET* __restrict__ Ahi, const ET* __restrict__ Alo,
    const ET* __restrict__ Bhi, const ET* __restrict__ Blo,
    int m0, int n0, int kc0, uint32_t st, int tid)
{
#pragma unroll
    for (int i = 0; i < 2; i++) {
        const int idx = tid + 256 * i;
        const int row = idx >> 2;
        const int u = idx & 3;
        const uint32_t doff = row * ROW_B + u * 16;
        const size_t aoff = (size_t)(m0 + row) * E_DIM + kc0 + u * 8;
        const size_t boff = (size_t)(n0 + row) * E_DIM + kc0 + u * 8;
        cp16(st + doff,             Ahi + aoff);
        cp16(st + ARR_B + doff,     Alo + aoff);
        cp16(st + 2 * ARR_B + doff, Bhi + boff);
        cp16(st + 3 * ARR_B + doff, Blo + boff);
    }
}

// ---------------------------------------------------------------------------
// HMMA GEMM: C = escale * (A @ B^T) + bias, NTERMS-term split.
// NTERMS=3: A_hi*B_hi + A_hi*B_lo + A_lo*B_hi.
// NTERMS=2: A_hi*B_hi + A_lo*B_hi  (== A * B_hi; drops A*B_lo ~ 2^-12 rel).
// MODE 1: per-chunk drain (chain <= 6), phi epilogue, row stride 2048.
// MODE 0: drain every 2 chunks, plain epilogue, row stride 1024.
// 256 threads, 8 warps, warp tile 32x64; zero-C drain-group starts;
// 4-stage cp.async ring, prefetch distance 3, single sync per k-iter.
// ---------------------------------------------------------------------------
template <int MODE, int NTERMS, typename ET>
__global__ void __launch_bounds__(256, 1) tc_gemm(
    const ET* __restrict__ Ahi, const ET* __restrict__ Alo,
    const ET* __restrict__ Bhi, const ET* __restrict__ Blo,
    const float* __restrict__ bias, float* __restrict__ Cout, float escale)
{
    extern __shared__ char smem[];
    const uint32_t sbase = smem_to_u32(smem);
    const int tid = threadIdx.x;
    const int wid = tid >> 5;
    const int lane = tid & 31;
    const int m0 = blockIdx.y * BM;
    const int n0 = blockIdx.x * BN;

    float* bias_s = (float*)(smem + SM_BIAS);
    if (tid < 128) bias_s[tid] = bias[n0 + tid];

    const int wm = wid >> 1;     // 0..3 -> rows wm*32
    const int wn = wid & 1;      // 0..1 -> cols wn*64
    const int g = lane >> 3;
    const int r = lane & 7;

    // preload 3 of 4 stages
#pragma unroll
    for (int s = 0; s < 3; s++) {
        load_stage(Ahi, Alo, Bhi, Blo, m0, n0, s * BK,
                   sbase + SM_STAGE0 + s * STAGE_B, tid);
        CP_COMMIT();
    }

    float accm[2][8][4];
    float accw[2][8][4];
#pragma unroll
    for (int mt = 0; mt < 2; mt++)
#pragma unroll
        for (int j = 0; j < 8; j++)
#pragma unroll
            for (int c = 0; c < 4; c++) accm[mt][j][c] = 0.f;

    const uint32_t a_row_off = (uint32_t)((wm * 32 + (g & 1) * 8 + r) * ROW_B + (g >> 1) * 16);
    const uint32_t b_row_off = (uint32_t)((wn * 64 + (g >> 1) * 8 + r) * ROW_B + (g & 1) * 16);

#pragma unroll 1
    for (int kt = 0; kt < NKT; kt++) {
        CP_WAIT2();        // slot kt%4 ready
        __syncthreads();   // all warps done reading slot (kt+3)%4

        // refill slot (kt+3)%4 — 3 iterations ahead
        if (kt + 3 < NKT)
            load_stage(Ahi, Alo, Bhi, Blo, m0, n0, (kt + 3) * BK,
                       sbase + SM_STAGE0 + ((kt + 3) % NSTAGE) * STAGE_B, tid);
        CP_COMMIT();

        const uint32_t st = sbase + SM_STAGE0 + (kt % NSTAGE) * STAGE_B;
        const uint32_t sA[2] = { st, st + ARR_B };
        const uint32_t sB[2] = { st + 2 * ARR_B, st + 3 * ARR_B };
        // MODE 1 (amplified phi path): fresh accumulator every chunk
        // MODE 0 (unamplified): fresh every 2 chunks
        const bool fresh = (MODE == 1) || ((kt & 1) == 0);
        const bool drain = (MODE == 1) || ((kt & 1) == 1);

#pragma unroll
        for (int ks = 0; ks < 2; ks++) {
            uint32_t afr[2][2][4];   // [mt][hl][4]
            uint32_t bfr[4][2][4];   // [jp][hl][4]
#pragma unroll
            for (int mt = 0; mt < 2; mt++)
#pragma unroll
                for (int hl = 0; hl < 2; hl++)
                    ldsm4(afr[mt][hl], sA[hl] + a_row_off + mt * (16 * ROW_B) + ks * 32);
#pragma unroll
            for (int jp = 0; jp < 4; jp++)
#pragma unroll
                for (int hl = 0; hl < (NTERMS == 3 ? 2 : 1); hl++)
                    ldsm4(bfr[jp][hl], sB[hl] + b_row_off + jp * (16 * ROW_B) + ks * 32);

#pragma unroll
            for (int t = 0; t < NTERMS; t++) {
                // NTERMS=3: (hh, hl, lh).  NTERMS=2: (hh, lh) — B_hi only.
                const int pa = (NTERMS == 3) ? ((t == 2) ? 1 : 0) : t;
                const int pb = (NTERMS == 3) ? ((t == 1) ? 1 : 0) : 0;
                const bool zc = fresh && ks == 0 && t == 0;
#pragma unroll
                for (int mt = 0; mt < 2; mt++)
#pragma unroll
                    for (int j = 0; j < 8; j++) {
                        const uint32_t* bj = &bfr[j >> 1][pb][(j & 1) * 2];
                        if (std::is_same<ET, __half>::value) {
                            if (zc) mma_f16_zc(accw[mt][j], afr[mt][pa], bj);
                            else    mma_f16(accw[mt][j], afr[mt][pa], bj);
                        } else {
                            if (zc) mma_bf16_zc(accw[mt][j], afr[mt][pa], bj);
                            else    mma_bf16(accw[mt][j], afr[mt][pa], bj);
                        }
                    }
            }
        }
        if (drain) {   // working -> master (IEEE-RN)
#pragma unroll
            for (int mt = 0; mt < 2; mt++)
#pragma unroll
                for (int j = 0; j < 8; j++)
#pragma unroll
                    for (int c = 0; c < 4; c++) accm[mt][j][c] += accw[mt][j][c];
        }
    }

    // ------------------------------ epilogue --------------------------------
    const int qr = lane >> 2;
    const int qc = (lane & 3) * 2;
#pragma unroll
    for (int mt = 0; mt < 2; mt++) {
        const int row0 = m0 + wm * 32 + mt * 16 + qr;
#pragma unroll
        for (int j = 0; j < 8; j++) {
            const int coll = wn * 64 + j * 8 + qc;
            const int col = n0 + coll;
            const float b0 = bias_s[coll], b1 = bias_s[coll + 1];
            if (MODE == 0) {
                float2 v0 = make_float2(accm[mt][j][0] * escale + b0,
                                        accm[mt][j][1] * escale + b1);
                float2 v1 = make_float2(accm[mt][j][2] * escale + b0,
                                        accm[mt][j][3] * escale + b1);
                *(float2*)(Cout + (size_t)row0 * E_DIM + col) = v0;
                *(float2*)(Cout + (size_t)(row0 + 8) * E_DIM + col) = v1;
            } else {
                const int h = col >> 6, k = col & 63;
                float s0, c0s, s1, c1s, s2, c2s, s3, c3s;
                __sincosf(accm[mt][j][0] * escale + b0, &s0, &c0s);
                __sincosf(accm[mt][j][1] * escale + b1, &s1, &c1s);
                __sincosf(accm[mt][j][2] * escale + b0, &s2, &c2s);
                __sincosf(accm[mt][j][3] * escale + b1, &s3, &c3s);
                float* p0 = Cout + (size_t)row0 * 2048 + h * 128 + k;
                float* p1 = Cout + (size_t)(row0 + 8) * 2048 + h * 128 + k;
                p0[0] = s0 * 0.125f; p0[1]  = s1 * 0.125f;
                p0[64] = c0s * 0.125f; p0[65] = c1s * 0.125f;
                p1[0] = s2 * 0.125f; p1[1]  = s3 * 0.125f;
                p1[64] = c2s * 0.125f; p1[65] = c3s * 0.125f;
            }
        }
    }
}

// ---------------------------------------------------------------------------
// Causal RFA scan, d-split x2, SCAN_NS timesteps per iteration.
// block bx = bh*2 + dh handles output dims d in [dh*32, dh*32+32).
// 256 threads: dl = tid&31, kg = tid>>5. Thread owns s[kg*16+j][dh*32+dl].
// R6-proven 2-sync skeleton. attn -> bf16 hi/lo.
// ---------------------------------------------------------------------------
__global__ void __launch_bounds__(256) rfa_scan(
    const float* __restrict__ phiq, const float* __restrict__ phik,
    const float* __restrict__ v, __nv_bfloat16* __restrict__ attn_hi,
    __nv_bfloat16* __restrict__ attn_lo)
{
    const int bx = blockIdx.x;       // bh*2 + dh
    const int dh = bx & 1;
    const int bh = bx >> 1;
    const int h = bh & 15;
    const int b = bh >> 4;
    const int tid = threadIdx.x;
    const int dl = tid & 31;
    const int kg = tid >> 5;         // 0..7

    __shared__ float s_pq[2][SCAN_NS][128], s_pk[2][SCAN_NS][128];
    __shared__ float s_v[2][SCAN_NS][32];
    __shared__ float s_z[128];
    __shared__ float s_red[SCAN_NS][256];
    __shared__ float s_qzp[SCAN_NS][4];

    float s_loc[16];
#pragma unroll
    for (int j = 0; j < 16; j++) s_loc[j] = 0.f;
    if (tid < 128) s_z[tid] = 0.f;

    const size_t phi_stride = (size_t)B_DIM * 2048;
    const size_t v_stride   = (size_t)B_DIM * 1024;
    const float* pq_base = phiq + (size_t)b * 2048 + h * 128;
    const float* pk_base = phik + (size_t)b * 2048 + h * 128;
    const float* v_base  = v    + (size_t)b * 1024 + h * 64 + dh * 32;
    const size_t o_off   = (size_t)b * 1024 + h * 64 + dh * 32;

    float ld_pq[SCAN_NS], ld_pk[SCAN_NS], ld_v[SCAN_NS];
#pragma unroll
    for (int s = 0; s < SCAN_NS; s++) { ld_pq[s] = 0.f; ld_pk[s] = 0.f; ld_v[s] = 0.f; }
    if (tid < 128) {
#pragma unroll
        for (int s = 0; s < SCAN_NS; s++) {
            ld_pq[s] = pq_base[(size_t)s * phi_stride + tid];
            ld_pk[s] = pk_base[(size_t)s * phi_stride + tid];
        }
    }
    if (tid < 32) {
#pragma unroll
        for (int s = 0; s < SCAN_NS; s++) ld_v[s] = v_base[(size_t)s * v_stride + tid];
    }
    int buf = 0;
    if (tid < 128) {
#pragma unroll
        for (int s = 0; s < SCAN_NS; s++) {
            s_pq[0][s][tid] = ld_pq[s];
            s_pk[0][s][tid] = ld_pk[s];
        }
    }
    if (tid < 32) {
#pragma unroll
        for (int s = 0; s < SCAN_NS; s++) s_v[0][s][tid] = ld_v[s];
    }
    __syncthreads();

    const int NGRP = T_DIM / SCAN_NS;
    for (int it = 0; it < NGRP; it++) {
        const size_t t0 = (size_t)(SCAN_NS * it);

        if (it + 1 < NGRP) {
            if (tid < 128) {
#pragma unroll
                for (int s = 0; s < SCAN_NS; s++) {
                    ld_pq[s] = pq_base[(t0 + SCAN_NS + s) * phi_stride + tid];
                    ld_pk[s] = pk_base[(t0 + SCAN_NS + s) * phi_stride + tid];
                }
            }
            if (tid < 32) {
#pragma unroll
                for (int s = 0; s < SCAN_NS; s++)
                    ld_v[s] = v_base[(t0 + SCAN_NS + s) * v_stride + tid];
            }
        }

        // s updates + q.s partials for SCAN_NS steps (sequential in s)
        {
            float vd[SCAN_NS];
            const float *pkp[SCAN_NS], *pqp[SCAN_NS];
#pragma unroll
            for (int s = 0; s < SCAN_NS; s++) {
                vd[s] = s_v[buf][s][dl];
                pkp[s] = &s_pk[buf][s][kg * 16];
                pqp[s] = &s_pq[buf][s][kg * 16];
            }
            float acc[SCAN_NS][4];
#pragma unroll
            for (int s = 0; s < SCAN_NS; s++)
#pragma unroll
                for (int c = 0; c < 4; c++) acc[s][c] = 0.f;
#pragma unroll
            for (int j = 0; j < 16; j += 4) {
#pragma unroll
                for (int s = 0; s < SCAN_NS; s++) {
                    float4 kk = *(const float4*)(pkp[s] + j);
                    float4 qq = *(const float4*)(pqp[s] + j);
                    s_loc[j + 0] += kk.x * vd[s]; acc[s][0] += qq.x * s_loc[j + 0];
                    s_loc[j + 1] += kk.y * vd[s]; acc[s][1] += qq.y * s_loc[j + 1];
                    s_loc[j + 2] += kk.z * vd[s]; acc[s][2] += qq.z * s_loc[j + 2];
                    s_loc[j + 3] += kk.w * vd[s]; acc[s][3] += qq.w * s_loc[j + 3];
                }
            }
#pragma unroll
            for (int s = 0; s < SCAN_NS; s++)
                s_red[s][tid] = (acc[s][0] + acc[s][1]) + (acc[s][2] + acc[s][3]);
        }

        // z updates + qz partials (threads 0..127)
        {
            float qzp[SCAN_NS];
#pragma unroll
            for (int s = 0; s < SCAN_NS; s++) qzp[s] = 0.f;
            if (tid < 128) {
                float z = s_z[tid];
#pragma unroll
                for (int s = 0; s < SCAN_NS; s++) {
                    z += s_pk[buf][s][tid];
                    qzp[s] = s_pq[buf][s][tid] * z;
                }
                s_z[tid] = z;
            }
#pragma unroll
            for (int off = 16; off; off >>= 1) {
#pragma unroll
                for (int s = 0; s < SCAN_NS; s++)
                    qzp[s] += __shfl_xor_sync(0xffffffffu, qzp[s], off);
            }
            if (tid < 128 && (tid & 31) == 0) {
#pragma unroll
                for (int s = 0; s < SCAN_NS; s++) s_qzp[s][tid >> 5] = qzp[s];
            }
        }
        __syncthreads();

        // finalize + write attn for this block's 32 d's
        if (tid < 32) {
#pragma unroll
            for (int stp = 0; stp < SCAN_NS; stp++) {
                const float* rd = s_red[stp];
                float qs = ((rd[dl] + rd[32 + dl]) + (rd[64 + dl] + rd[96 + dl])) +
                           ((rd[128 + dl] + rd[160 + dl]) + (rd[192 + dl] + rd[224 + dl]));
                float qz = (s_qzp[stp][0] + s_qzp[stp][1]) +
                           (s_qzp[stp][2] + s_qzp[stp][3]);
                qz = fmaxf(qz, EPS_RFA);
                float o = qs / qz;
                __nv_bfloat16 hv = __float2bfloat16(o);
                size_t idx = (t0 + stp) * v_stride + o_off + dl;
                attn_hi[idx] = hv;
                attn_lo[idx] = __float2bfloat16(o - __bfloat162float(hv));
            }
        }

        buf ^= 1;
        if (it + 1 < NGRP) {
            if (tid < 128) {
#pragma unroll
                for (int s = 0; s < SCAN_NS; s++) {
                    s_pq[buf][s][tid] = ld_pq[s];
                    s_pk[buf][s][tid] = ld_pk[s];
                }
            }
            if (tid < 32) {
#pragma unroll
                for (int s = 0; s < SCAN_NS; s++) s_v[buf][s][tid] = ld_v[s];
            }
        }
        __syncthreads();
    }
}

// ---------------------------------------------------------------------------
extern "C" void kernel_launch(void* const* d_in, const int* in_sizes, int n_in,
                              void* d_out, int out_size)
{
    const float* x  = (const float*)d_in[0];
    const float* rm = (const float*)d_in[1];
    const float* Wq = (const float*)d_in[2];
    const float* bq = (const float*)d_in[3];
    const float* Wk = (const float*)d_in[4];
    const float* bk = (const float*)d_in[5];
    const float* Wv = (const float*)d_in[6];
    const float* bv = (const float*)d_in[7];
    const float* Wo = (const float*)d_in[8];
    const float* bo = (const float*)d_in[9];
    float* out = (float*)d_out;

    __half *x_hi, *x_lo, *Wq_hi, *Wq_lo, *Wk_hi, *Wk_lo, *Wv_hi, *Wv_lo;
    __nv_bfloat16 *Wo_hi, *Wo_lo, *attn_hi, *attn_lo;
    float *bq_eff, *bk_eff, *vbuf, *phiq, *phik;
    cudaGetSymbolAddress((void**)&x_hi, g_x_hi);
    cudaGetSymbolAddress((void**)&x_lo, g_x_lo);
    cudaGetSymbolAddress((void**)&Wq_hi, g_Wq_hi);
    cudaGetSymbolAddress((void**)&Wq_lo, g_Wq_lo);
    cudaGetSymbolAddress((void**)&Wk_hi, g_Wk_hi);
    cudaGetSymbolAddress((void**)&Wk_lo, g_Wk_lo);
    cudaGetSymbolAddress((void**)&Wv_hi, g_Wv_hi);
    cudaGetSymbolAddress((void**)&Wv_lo, g_Wv_lo);
    cudaGetSymbolAddress((void**)&Wo_hi, g_Wo_hi);
    cudaGetSymbolAddress((void**)&Wo_lo, g_Wo_lo);
    cudaGetSymbolAddress((void**)&attn_hi, g_attn_hi);
    cudaGetSymbolAddress((void**)&attn_lo, g_attn_lo);
    cudaGetSymbolAddress((void**)&bq_eff, g_bq_eff);
    cudaGetSymbolAddress((void**)&bk_eff, g_bk_eff);
    cudaGetSymbolAddress((void**)&vbuf, g_v);
    cudaGetSymbolAddress((void**)&phiq, g_phiq);
    cudaGetSymbolAddress((void**)&phik, g_phik);

    cudaFuncSetAttribute((const void*)tc_gemm<1, 3, __half>,
                         cudaFuncAttributeMaxDynamicSharedMemorySize, SM_TOTAL);
    cudaFuncSetAttribute((const void*)tc_gemm<0, 2, __half>,
                         cudaFuncAttributeMaxDynamicSharedMemorySize, SM_TOTAL);
    cudaFuncSetAttribute((const void*)tc_gemm<0, 3, __nv_bfloat16>,
                         cudaFuncAttributeMaxDynamicSharedMemorySize, SM_TOTAL);

    // conversions + weight prep: x scaled x256 (fp16 lo stays normal),
    // fp16 weights x64; bf16 Wo unscaled.
    f32_to_f16hl<<<TB * E_DIM / 1024, 256>>>(x, x_hi, x_lo, TB * E_DIM, 256.0f);
    prep_weff<<<dim3(16, 16), 256>>>(rm, Wq, bq, Wq_hi, Wq_lo, bq_eff, 0.125f);
    prep_weff<<<dim3(16, 16), 256>>>(rm, Wk, bk, Wk_hi, Wk_lo, bk_eff, 1.0f);
    f32_to_f16hl<<<E_DIM * E_DIM / 1024, 256>>>(Wv, Wv_hi, Wv_lo, E_DIM * E_DIM, 64.0f);
    f32_to_bf16hl<<<E_DIM * E_DIM / 1024, 256>>>(Wo, Wo_hi, Wo_lo, E_DIM * E_DIM);

    // tensor-core GEMMs (escale undoes x256 * x64)
    dim3 gg(E_DIM / BN, TB / BM);   // (8, 128)
    const float inv = 1.0f / 16384.0f;
    tc_gemm<1, 3, __half><<<gg, 256, SM_TOTAL>>>(x_hi, x_lo, Wq_hi, Wq_lo, bq_eff, phiq, inv);
    tc_gemm<1, 3, __half><<<gg, 256, SM_TOTAL>>>(x_hi, x_lo, Wk_hi, Wk_lo, bk_eff, phik, inv);
    // v: 2-term (A * B_hi) — unamplified path, ~2^-12 rel error
    tc_gemm<0, 2, __half><<<gg, 256, SM_TOTAL>>>(x_hi, x_lo, Wv_hi, Wv_lo, bv, vbuf, inv);

    // causal scan, d-split x2, 4 timesteps/iter (256 blocks; attn bf16 split)
    rfa_scan<<<B_DIM * H_DIM * 2, 256>>>(phiq, phik, vbuf, attn_hi, attn_lo);

    // output projection (bf16 3-term, unamplified error path)
    tc_gemm<0, 3, __nv_bfloat16><<<gg, 256, SM_TOTAL>>>(attn_hi, attn_lo, Wo_hi, Wo_lo, bo, out, 1.0f);
}

// round 15
// speedup vs baseline: 1.1028x; 1.0631x over previous
#include <cuda_runtime.h>
#include <cuda_fp16.h>
#include <cuda_bf16.h>
#include <cstdint>
#include <type_traits>

// ---------------------------------------------------------------------------
// CausalAttention (random-feature attention) — mma.sync split GEMMs.
// phi GEMMs: fp16 3-term, per-chunk RN drain — amplified path.
// v GEMM:    fp16 2-term (drop B_lo) — unamplified, ~2^-12 rel.
// out GEMM:  fp16 2-term (drop A_lo) on per-row dynamically scaled attn.
// Scan: d-split x2, 4 timesteps/iter, writes fp32 attn; rowscale pass
// converts to fp16 with per-row scale (handles qz->EPS spikes).
// ---------------------------------------------------------------------------

#define T_DIM 2048
#define B_DIM 8
#define E_DIM 1024
#define H_DIM 16
#define TB    (T_DIM * B_DIM)          // 16384 rows
#define EPS_RFA 1e-6f

#define BM 128
#define BN 128
#define BK 32
#define NKT (E_DIM / BK)                // 32
#define ROW_B 80
#define ARR_B (128 * ROW_B)
#define STAGE_B (4 * ARR_B)             // 40960
#define NSTAGE 4
#define SM_BIAS 0
#define SM_STAGE0 1024
#define SM_TOTAL (SM_STAGE0 + NSTAGE * STAGE_B)   // 164864

#define SCAN_NS 4                       // timesteps per scan iteration

// ------------------------- scratch (static device) -------------------------
__device__ __half g_x_hi[TB * E_DIM];
__device__ __half g_x_lo[TB * E_DIM];
__device__ __half g_Wq_hi[E_DIM * E_DIM];
__device__ __half g_Wq_lo[E_DIM * E_DIM];
__device__ __half g_Wk_hi[E_DIM * E_DIM];
__device__ __half g_Wk_lo[E_DIM * E_DIM];
__device__ __half g_Wv_hi[E_DIM * E_DIM];
__device__ __half g_Wv_lo[E_DIM * E_DIM];
__device__ __half g_Wo_hi[E_DIM * E_DIM];
__device__ __half g_Wo_lo[E_DIM * E_DIM];
__device__ float g_bq_eff[E_DIM];
__device__ float g_bk_eff[E_DIM];
__device__ float g_v   [TB * E_DIM];
__device__ float g_phiq[(size_t)TB * 2048];
__device__ float g_phik[(size_t)TB * 2048];
__device__ float g_attn_f32[TB * E_DIM];
__device__ __half g_attn_hi[TB * E_DIM];
__device__ float g_inv_s[TB];

// ----------------------------- PTX helpers ---------------------------------
__device__ __forceinline__ uint32_t smem_to_u32(const void* p) {
    uint32_t a;
    asm("{ .reg .u64 t; cvta.to.shared.u64 t, %1; cvt.u32.u64 %0, t; }" : "=r"(a) : "l"(p));
    return a;
}
__device__ __forceinline__ void cp16(uint32_t dst, const void* src) {
    asm volatile("cp.async.cg.shared.global [%0], [%1], 16;" :: "r"(dst), "l"(src) : "memory");
}
#define CP_COMMIT() asm volatile("cp.async.commit_group;" ::: "memory")
#define CP_WAIT2()  asm volatile("cp.async.wait_group 2;" ::: "memory")

__device__ __forceinline__ void ldsm4(uint32_t* r, uint32_t addr) {
    asm volatile("ldmatrix.sync.aligned.m8n8.x4.shared.b16 {%0,%1,%2,%3}, [%4];"
                 : "=r"(r[0]), "=r"(r[1]), "=r"(r[2]), "=r"(r[3]) : "r"(addr));
}
__device__ __forceinline__ void mma_f16(float* d, const uint32_t* a, const uint32_t* b) {
    asm volatile(
        "mma.sync.aligned.m16n8k16.row.col.f32.f16.f16.f32 "
        "{%0,%1,%2,%3}, {%4,%5,%6,%7}, {%8,%9}, {%0,%1,%2,%3};"
        : "+f"(d[0]), "+f"(d[1]), "+f"(d[2]), "+f"(d[3])
        : "r"(a[0]), "r"(a[1]), "r"(a[2]), "r"(a[3]), "r"(b[0]), "r"(b[1]));
}
__device__ __forceinline__ void mma_f16_zc(float* d, const uint32_t* a, const uint32_t* b) {
    asm volatile(
        "mma.sync.aligned.m16n8k16.row.col.f32.f16.f16.f32 "
        "{%0,%1,%2,%3}, {%4,%5,%6,%7}, {%8,%9}, {%10,%10,%10,%10};"
        : "=f"(d[0]), "=f"(d[1]), "=f"(d[2]), "=f"(d[3])
        : "r"(a[0]), "r"(a[1]), "r"(a[2]), "r"(a[3]), "r"(b[0]), "r"(b[1]),
          "f"(0.0f));
}

// ---------------------------------------------------------------------------
// fp32 -> fp16 hi/lo split (with pre-scale)
// ---------------------------------------------------------------------------
__global__ void __launch_bounds__(256) f32_to_f16hl(
    const float* __restrict__ in, __half* __restrict__ hi,
    __half* __restrict__ lo, int n, float scale)
{
    int i = (blockIdx.x * 256 + threadIdx.x) * 4;
    if (i >= n) return;
    float4 v = *(const float4*)(in + i);
    float a[4] = {v.x * scale, v.y * scale, v.z * scale, v.w * scale};
    __half h[4], l[4];
#pragma unroll
    for (int j = 0; j < 4; j++) {
        h[j] = __float2half_rn(a[j]);
        l[j] = __float2half_rn(a[j] - __half2float(h[j]));
    }
    *(__half2*)(hi + i)     = __halves2half2(h[0], h[1]);
    *(__half2*)(hi + i + 2) = __halves2half2(h[2], h[3]);
    *(__half2*)(lo + i)     = __halves2half2(l[0], l[1]);
    *(__half2*)(lo + i + 2) = __halves2half2(l[2], l[3]);
}

// ---------------------------------------------------------------------------
// Per-row dynamic scale of attn: one warp per (t,b) row of 1024 floats.
// ahi[row,:] = fp16(attn[row,:] * s),  s = 16384 / max(rowmax, 1)
// inv_s[row] = 1/s. Spiked rows (qz->EPS) stay in fp16 range; precision is
// 2^-12 relative to rowmax, and spiked outputs are spike-dominated.
// ---------------------------------------------------------------------------
__global__ void __launch_bounds__(256) rowscale(
    const float* __restrict__ attn, __half* __restrict__ ahi,
    float* __restrict__ inv_s)
{
    const int row = blockIdx.x * 8 + (threadIdx.x >> 5);
    const int lane = threadIdx.x & 31;
    const float* src = attn + (size_t)row * E_DIM;
    float vals[32];
    float m = 0.f;
#pragma unroll
    for (int i = 0; i < 32; i++) {
        vals[i] = src[lane + i * 32];
        m = fmaxf(m, fabsf(vals[i]));
    }
#pragma unroll
    for (int off = 16; off; off >>= 1)
        m = fmaxf(m, __shfl_xor_sync(0xffffffffu, m, off));
    const float sr = 16384.f / fmaxf(m, 1.f);
    __half* dst = ahi + (size_t)row * E_DIM;
#pragma unroll
    for (int i = 0; i < 32; i++)
        dst[lane + i * 32] = __float2half_rn(vals[i] * sr);
    if (lane == 0) inv_s[row] = 1.f / sr;
}

// ---------------------------------------------------------------------------
// Weight prep: Weff[h*64+k, e] = scale * sum_d rm[h,k,d] * W[h*64+d, e]
// matrix written as fp16 hi/lo with extra x64; beff fp32 (logical scale).
// ---------------------------------------------------------------------------
__global__ void __launch_bounds__(256) prep_weff(
    const float* __restrict__ rm, const float* __restrict__ W,
    const float* __restrict__ bvec, __half* __restrict__ Whi,
    __half* __restrict__ Wlo, float* __restrict__ beff, float scale)
{
    const int h  = blockIdx.y;
    const int e0 = blockIdx.x * 64;
    const int tid = threadIdx.x;

    __shared__ float rs[64][65];
    __shared__ float ws[64][65];

    for (int i = tid; i < 4096; i += 256) {
        int k = i >> 6, dd = i & 63;
        rs[k][dd] = rm[h * 4096 + i];
    }
    for (int i = tid; i < 4096; i += 256) {
        int dd = i >> 6, e = i & 63;
        ws[dd][e] = W[(size_t)(h * 64 + dd) * E_DIM + e0 + e];
    }
    __syncthreads();

    const int tk = (tid >> 4) * 4;
    const int te = (tid & 15) * 4;
    float acc[4][4];
#pragma unroll
    for (int i = 0; i < 4; i++)
#pragma unroll
        for (int j = 0; j < 4; j++) acc[i][j] = 0.f;

#pragma unroll 8
    for (int dd = 0; dd < 64; dd++) {
        float a0 = rs[tk + 0][dd], a1 = rs[tk + 1][dd];
        float a2 = rs[tk + 2][dd], a3 = rs[tk + 3][dd];
        float b0 = ws[dd][te + 0], b1 = ws[dd][te + 1];
        float b2 = ws[dd][te + 2], b3 = ws[dd][te + 3];
        acc[0][0] += a0 * b0; acc[0][1] += a0 * b1; acc[0][2] += a0 * b2; acc[0][3] += a0 * b3;
        acc[1][0] += a1 * b0; acc[1][1] += a1 * b1; acc[1][2] += a1 * b2; acc[1][3] += a1 * b3;
        acc[2][0] += a2 * b0; acc[2][1] += a2 * b1; acc[2][2] += a2 * b2; acc[2][3] += a2 * b3;
        acc[3][0] += a3 * b0; acc[3][1] += a3 * b1; acc[3][2] += a3 * b2; acc[3][3] += a3 * b3;
    }
#pragma unroll
    for (int i = 0; i < 4; i++)
#pragma unroll
        for (int j = 0; j < 4; j++) {
            float val = 64.f * scale * acc[i][j];
            size_t idx = (size_t)(h * 64 + tk + i) * E_DIM + e0 + te + j;
            __half hv = __float2half_rn(val);
            Whi[idx] = hv;
            Wlo[idx] = __float2half_rn(val - __half2float(hv));
        }

    if (blockIdx.x == 0 && tid < 64) {
        float s = 0.f;
        for (int dd = 0; dd < 64; dd++) s += rs[tid][dd] * bvec[h * 64 + dd];
        beff[h * 64 + tid] = scale * s;
    }
}

// ---------------------------------------------------------------------------
// one k-stage loader — loads only the arrays a TMODE uses
// ---------------------------------------------------------------------------
template <bool LA, bool LB>
__device__ __forceinline__ void load_stage(
    const __half* __restrict__ Ahi, const __half* __restrict__ Alo,
    const __half* __restrict__ Bhi, const __half* __restrict__ Blo,
    int m0, int n0, int kc0, uint32_t st, int tid)
{
#pragma unroll
    for (int i = 0; i < 2; i++) {
        const int idx = tid + 256 * i;
        const int row = idx >> 2;
        const int u = idx & 3;
        const uint32_t doff = row * ROW_B + u * 16;
        const size_t aoff = (size_t)(m0 + row) * E_DIM + kc0 + u * 8;
        const size_t boff = (size_t)(n0 + row) * E_DIM + kc0 + u * 8;
        cp16(st + doff, Ahi + aoff);
        if (LA) cp16(st + ARR_B + doff, Alo + aoff);
        cp16(st + 2 * ARR_B + doff, Bhi + boff);
        if (LB) cp16(st + 3 * ARR_B + doff, Blo + boff);
    }
}

// ---------------------------------------------------------------------------
// HMMA GEMM: split fp16, TMODE selects the term set:
//   TMODE 0: A_hi*B_hi + A_hi*B_lo + A_lo*B_hi   (3-term)
//   TMODE 1: A_hi*B_hi + A_lo*B_hi               (2-term, drop B_lo)
//   TMODE 2: A_hi*B_hi + A_hi*B_lo               (2-term, drop A_lo)
// MODE 1: per-chunk drain, phi epilogue (row stride 2048).
// MODE 0: drain every 2 chunks, plain epilogue: escale*acc + bias.
// MODE 2: drain every 2 chunks, row-scaled epilogue:
//         (escale*rscale[row])*acc + bias.
// ---------------------------------------------------------------------------
template <int MODE, int TMODE>
__global__ void __launch_bounds__(256, 1) tc_gemm(
    const __half* __restrict__ Ahi, const __half* __restrict__ Alo,
    const __half* __restrict__ Bhi, const __half* __restrict__ Blo,
    const float* __restrict__ bias, float* __restrict__ Cout, float escale,
    const float* __restrict__ rscale)
{
    extern __shared__ char smem[];
    const uint32_t sbase = smem_to_u32(smem);
    const int tid = threadIdx.x;
    const int wid = tid >> 5;
    const int lane = tid & 31;
    const int m0 = blockIdx.y * BM;
    const int n0 = blockIdx.x * BN;

    float* bias_s = (float*)(smem + SM_BIAS);
    if (tid < 128) bias_s[tid] = bias[n0 + tid];

    const int wm = wid >> 1;
    const int wn = wid & 1;
    const int g = lane >> 3;
    const int r = lane & 7;

    constexpr bool LA = (TMODE != 2);
    constexpr bool LB = (TMODE != 1);
    constexpr int NT = (TMODE == 0) ? 3 : 2;

#pragma unroll
    for (int s = 0; s < 3; s++) {
        load_stage<LA, LB>(Ahi, Alo, Bhi, Blo, m0, n0, s * BK,
                           sbase + SM_STAGE0 + s * STAGE_B, tid);
        CP_COMMIT();
    }

    float accm[2][8][4];
    float accw[2][8][4];
#pragma unroll
    for (int mt = 0; mt < 2; mt++)
#pragma unroll
        for (int j = 0; j < 8; j++)
#pragma unroll
            for (int c = 0; c < 4; c++) accm[mt][j][c] = 0.f;

    const uint32_t a_row_off = (uint32_t)((wm * 32 + (g & 1) * 8 + r) * ROW_B + (g >> 1) * 16);
    const uint32_t b_row_off = (uint32_t)((wn * 64 + (g >> 1) * 8 + r) * ROW_B + (g & 1) * 16);

#pragma unroll 1
    for (int kt = 0; kt < NKT; kt++) {
        CP_WAIT2();
        __syncthreads();

        if (kt + 3 < NKT)
            load_stage<LA, LB>(Ahi, Alo, Bhi, Blo, m0, n0, (kt + 3) * BK,
                               sbase + SM_STAGE0 + ((kt + 3) % NSTAGE) * STAGE_B, tid);
        CP_COMMIT();

        const uint32_t st = sbase + SM_STAGE0 + (kt % NSTAGE) * STAGE_B;
        const uint32_t sA[2] = { st, st + ARR_B };
        const uint32_t sB[2] = { st + 2 * ARR_B, st + 3 * ARR_B };
        const bool fresh = (MODE == 1) || ((kt & 1) == 0);
        const bool drain = (MODE == 1) || ((kt & 1) == 1);

#pragma unroll
        for (int ks = 0; ks < 2; ks++) {
            uint32_t afr[2][2][4];
            uint32_t bfr[4][2][4];
#pragma unroll
            for (int mt = 0; mt < 2; mt++)
#pragma unroll
                for (int hl = 0; hl < (LA ? 2 : 1); hl++)
                    ldsm4(afr[mt][hl], sA[hl] + a_row_off + mt * (16 * ROW_B) + ks * 32);
#pragma unroll
            for (int jp = 0; jp < 4; jp++)
#pragma unroll
                for (int hl = 0; hl < (LB ? 2 : 1); hl++)
                    ldsm4(bfr[jp][hl], sB[hl] + b_row_off + jp * (16 * ROW_B) + ks * 32);

#pragma unroll
            for (int t = 0; t < NT; t++) {
                // TMODE 0: (0,0),(0,1),(1,0); TMODE 1: (0,0),(1,0);
                // TMODE 2: (0,0),(0,1)
                const int pa = (TMODE == 0) ? ((t == 2) ? 1 : 0)
                             : (TMODE == 1) ? t : 0;
                const int pb = (TMODE == 0) ? ((t == 1) ? 1 : 0)
                             : (TMODE == 1) ? 0 : t;
                const bool zc = fresh && ks == 0 && t == 0;
#pragma unroll
                for (int mt = 0; mt < 2; mt++)
#pragma unroll
                    for (int j = 0; j < 8; j++) {
                        const uint32_t* bj = &bfr[j >> 1][pb][(j & 1) * 2];
                        if (zc) mma_f16_zc(accw[mt][j], afr[mt][pa], bj);
                        else    mma_f16(accw[mt][j], afr[mt][pa], bj);
                    }
            }
        }
        if (drain) {
#pragma unroll
            for (int mt = 0; mt < 2; mt++)
#pragma unroll
                for (int j = 0; j < 8; j++)
#pragma unroll
                    for (int c = 0; c < 4; c++) accm[mt][j][c] += accw[mt][j][c];
        }
    }

    // ------------------------------ epilogue --------------------------------
    const int qr = lane >> 2;
    const int qc = (lane & 3) * 2;
#pragma unroll
    for (int mt = 0; mt < 2; mt++) {
        const int row0 = m0 + wm * 32 + mt * 16 + qr;
        float es0 = escale, es1 = escale;
        if (MODE == 2) {
            es0 = escale * rscale[row0];
            es1 = escale * rscale[row0 + 8];
        }
#pragma unroll
        for (int j = 0; j < 8; j++) {
            const int coll = wn * 64 + j * 8 + qc;
            const int col = n0 + coll;
            const float b0 = bias_s[coll], b1 = bias_s[coll + 1];
            if (MODE != 1) {
                float2 v0 = make_float2(accm[mt][j][0] * es0 + b0,
                                        accm[mt][j][1] * es0 + b1);
                float2 v1 = make_float2(accm[mt][j][2] * es1 + b0,
                                        accm[mt][j][3] * es1 + b1);
                *(float2*)(Cout + (size_t)row0 * E_DIM + col) = v0;
                *(float2*)(Cout + (size_t)(row0 + 8) * E_DIM + col) = v1;
            } else {
                const int h = col >> 6, k = col & 63;
                float s0, c0s, s1, c1s, s2, c2s, s3, c3s;
                __sincosf(accm[mt][j][0] * escale + b0, &s0, &c0s);
                __sincosf(accm[mt][j][1] * escale + b1, &s1, &c1s);
                __sincosf(accm[mt][j][2] * escale + b0, &s2, &c2s);
                __sincosf(accm[mt][j][3] * escale + b1, &s3, &c3s);
                float* p0 = Cout + (size_t)row0 * 2048 + h * 128 + k;
                float* p1 = Cout + (size_t)(row0 + 8) * 2048 + h * 128 + k;
                p0[0] = s0 * 0.125f; p0[1]  = s1 * 0.125f;
                p0[64] = c0s * 0.125f; p0[65] = c1s * 0.125f;
                p1[0] = s2 * 0.125f; p1[1]  = s3 * 0.125f;
                p1[64] = c2s * 0.125f; p1[65] = c3s * 0.125f;
            }
        }
    }
}

// ---------------------------------------------------------------------------
// Causal RFA scan, d-split x2, SCAN_NS timesteps per iteration.
// Writes plain fp32 attn (rowscale pass converts for the out GEMM).
// ---------------------------------------------------------------------------
__global__ void __launch_bounds__(256) rfa_scan(
    const float* __restrict__ phiq, const float* __restrict__ phik,
    const float* __restrict__ v, float* __restrict__ attn)
{
    const int bx = blockIdx.x;
    const int dh = bx & 1;
    const int bh = bx >> 1;
    const int h = bh & 15;
    const int b = bh >> 4;
    const int tid = threadIdx.x;
    const int dl = tid & 31;
    const int kg = tid >> 5;

    __shared__ float s_pq[2][SCAN_NS][128], s_pk[2][SCAN_NS][128];
    __shared__ float s_v[2][SCAN_NS][32];
    __shared__ float s_z[128];
    __shared__ float s_red[SCAN_NS][256];
    __shared__ float s_qzp[SCAN_NS][4];

    float s_loc[16];
#pragma unroll
    for (int j = 0; j < 16; j++) s_loc[j] = 0.f;
    if (tid < 128) s_z[tid] = 0.f;

    const size_t phi_stride = (size_t)B_DIM * 2048;
    const size_t v_stride   = (size_t)B_DIM * 1024;
    const float* pq_base = phiq + (size_t)b * 2048 + h * 128;
    const float* pk_base = phik + (size_t)b * 2048 + h * 128;
    const float* v_base  = v    + (size_t)b * 1024 + h * 64 + dh * 32;
    const size_t o_off   = (size_t)b * 1024 + h * 64 + dh * 32;

    float ld_pq[SCAN_NS], ld_pk[SCAN_NS], ld_v[SCAN_NS];
#pragma unroll
    for (int s = 0; s < SCAN_NS; s++) { ld_pq[s] = 0.f; ld_pk[s] = 0.f; ld_v[s] = 0.f; }
    if (tid < 128) {
#pragma unroll
        for (int s = 0; s < SCAN_NS; s++) {
            ld_pq[s] = pq_base[(size_t)s * phi_stride + tid];
            ld_pk[s] = pk_base[(size_t)s * phi_stride + tid];
        }
    }
    if (tid < 32) {
#pragma unroll
        for (int s = 0; s < SCAN_NS; s++) ld_v[s] = v_base[(size_t)s * v_stride + tid];
    }
    int buf = 0;
    if (tid < 128) {
#pragma unroll
        for (int s = 0; s < SCAN_NS; s++) {
            s_pq[0][s][tid] = ld_pq[s];
            s_pk[0][s][tid] = ld_pk[s];
        }
    }
    if (tid < 32) {
#pragma unroll
        for (int s = 0; s < SCAN_NS; s++) s_v[0][s][tid] = ld_v[s];
    }
    __syncthreads();

    const int NGRP = T_DIM / SCAN_NS;
    for (int it = 0; it < NGRP; it++) {
        const size_t t0 = (size_t)(SCAN_NS * it);

        if (it + 1 < NGRP) {
            if (tid < 128) {
#pragma unroll
                for (int s = 0; s < SCAN_NS; s++) {
                    ld_pq[s] = pq_base[(t0 + SCAN_NS + s) * phi_stride + tid];
                    ld_pk[s] = pk_base[(t0 + SCAN_NS + s) * phi_stride + tid];
                }
            }
            if (tid < 32) {
#pragma unroll
                for (int s = 0; s < SCAN_NS; s++)
                    ld_v[s] = v_base[(t0 + SCAN_NS + s) * v_stride + tid];
            }
        }

        {
            float vd[SCAN_NS];
            const float *pkp[SCAN_NS], *pqp[SCAN_NS];
#pragma unroll
            for (int s = 0; s < SCAN_NS; s++) {
                vd[s] = s_v[buf][s][dl];
                pkp[s] = &s_pk[buf][s][kg * 16];
                pqp[s] = &s_pq[buf][s][kg * 16];
            }
            float acc[SCAN_NS][4];
#pragma unroll
            for (int s = 0; s < SCAN_NS; s++)
#pragma unroll
                for (int c = 0; c < 4; c++) acc[s][c] = 0.f;
#pragma unroll
            for (int j = 0; j < 16; j += 4) {
#pragma unroll
                for (int s = 0; s < SCAN_NS; s++) {
                    float4 kk = *(const float4*)(pkp[s] + j);
                    float4 qq = *(const float4*)(pqp[s] + j);
                    s_loc[j + 0] += kk.x * vd[s]; acc[s][0] += qq.x * s_loc[j + 0];
                    s_loc[j + 1] += kk.y * vd[s]; acc[s][1] += qq.y * s_loc[j + 1];
                    s_loc[j + 2] += kk.z * vd[s]; acc[s][2] += qq.z * s_loc[j + 2];
                    s_loc[j + 3] += kk.w * vd[s]; acc[s][3] += qq.w * s_loc[j + 3];
                }
            }
#pragma unroll
            for (int s = 0; s < SCAN_NS; s++)
                s_red[s][tid] = (acc[s][0] + acc[s][1]) + (acc[s][2] + acc[s][3]);
        }

        {
            float qzp[SCAN_NS];
#pragma unroll
            for (int s = 0; s < SCAN_NS; s++) qzp[s] = 0.f;
            if (tid < 128) {
                float z = s_z[tid];
#pragma unroll
                for (int s = 0; s < SCAN_NS; s++) {
                    z += s_pk[buf][s][tid];
                    qzp[s] = s_pq[buf][s][tid] * z;
                }
                s_z[tid] = z;
            }
#pragma unroll
            for (int off = 16; off; off >>= 1) {
#pragma unroll
                for (int s = 0; s < SCAN_NS; s++)
                    qzp[s] += __shfl_xor_sync(0xffffffffu, qzp[s], off);
            }
            if (tid < 128 && (tid & 31) == 0) {
#pragma unroll
                for (int s = 0; s < SCAN_NS; s++) s_qzp[s][tid >> 5] = qzp[s];
            }
        }
        __syncthreads();

        if (tid < 32) {
#pragma unroll
            for (int stp = 0; stp < SCAN_NS; stp++) {
                const float* rd = s_red[stp];
                float qs = ((rd[dl] + rd[32 + dl]) + (rd[64 + dl] + rd[96 + dl])) +
                           ((rd[128 + dl] + rd[160 + dl]) + (rd[192 + dl] + rd[224 + dl]));
                float qz = (s_qzp[stp][0] + s_qzp[stp][1]) +
                           (s_qzp[stp][2] + s_qzp[stp][3]);
                qz = fmaxf(qz, EPS_RFA);
                attn[(t0 + stp) * v_stride + o_off + dl] = qs / qz;
            }
        }

        buf ^= 1;
        if (it + 1 < NGRP) {
            if (tid < 128) {
#pragma unroll
                for (int s = 0; s < SCAN_NS; s++) {
                    s_pq[buf][s][tid] = ld_pq[s];
                    s_pk[buf][s][tid] = ld_pk[s];
                }
            }
            if (tid < 32) {
#pragma unroll
                for (int s = 0; s < SCAN_NS; s++) s_v[buf][s][tid] = ld_v[s];
            }
        }
        __syncthreads();
    }
}

// ---------------------------------------------------------------------------
extern "C" void kernel_launch(void* const* d_in, const int* in_sizes, int n_in,
                              void* d_out, int out_size)
{
    const float* x  = (const float*)d_in[0];
    const float* rm = (const float*)d_in[1];
    const float* Wq = (const float*)d_in[2];
    const float* bq = (const float*)d_in[3];
    const float* Wk = (const float*)d_in[4];
    const float* bk = (const float*)d_in[5];
    const float* Wv = (const float*)d_in[6];
    const float* bv = (const float*)d_in[7];
    const float* Wo = (const float*)d_in[8];
    const float* bo = (const float*)d_in[9];
    float* out = (float*)d_out;

    __half *x_hi, *x_lo, *Wq_hi, *Wq_lo, *Wk_hi, *Wk_lo, *Wv_hi, *Wv_lo,
           *Wo_hi, *Wo_lo, *attn_hi;
    float *bq_eff, *bk_eff, *vbuf, *phiq, *phik, *attn_f32, *inv_s;
    cudaGetSymbolAddress((void**)&x_hi, g_x_hi);
    cudaGetSymbolAddress((void**)&x_lo, g_x_lo);
    cudaGetSymbolAddress((void**)&Wq_hi, g_Wq_hi);
    cudaGetSymbolAddress((void**)&Wq_lo, g_Wq_lo);
    cudaGetSymbolAddress((void**)&Wk_hi, g_Wk_hi);
    cudaGetSymbolAddress((void**)&Wk_lo, g_Wk_lo);
    cudaGetSymbolAddress((void**)&Wv_hi, g_Wv_hi);
    cudaGetSymbolAddress((void**)&Wv_lo, g_Wv_lo);
    cudaGetSymbolAddress((void**)&Wo_hi, g_Wo_hi);
    cudaGetSymbolAddress((void**)&Wo_lo, g_Wo_lo);
    cudaGetSymbolAddress((void**)&attn_hi, g_attn_hi);
    cudaGetSymbolAddress((void**)&attn_f32, g_attn_f32);
    cudaGetSymbolAddress((void**)&inv_s, g_inv_s);
    cudaGetSymbolAddress((void**)&bq_eff, g_bq_eff);
    cudaGetSymbolAddress((void**)&bk_eff, g_bk_eff);
    cudaGetSymbolAddress((void**)&vbuf, g_v);
    cudaGetSymbolAddress((void**)&phiq, g_phiq);
    cudaGetSymbolAddress((void**)&phik, g_phik);

    cudaFuncSetAttribute((const void*)tc_gemm<1, 0>,
                         cudaFuncAttributeMaxDynamicSharedMemorySize, SM_TOTAL);
    cudaFuncSetAttribute((const void*)tc_gemm<0, 1>,
                         cudaFuncAttributeMaxDynamicSharedMemorySize, SM_TOTAL);
    cudaFuncSetAttribute((const void*)tc_gemm<2, 2>,
                         cudaFuncAttributeMaxDynamicSharedMemorySize, SM_TOTAL);

    // conversions + weight prep: x scaled x256, weights x64 (fp16 lo range).
    f32_to_f16hl<<<TB * E_DIM / 1024, 256>>>(x, x_hi, x_lo, TB * E_DIM, 256.0f);
    prep_weff<<<dim3(16, 16), 256>>>(rm, Wq, bq, Wq_hi, Wq_lo, bq_eff, 0.125f);
    prep_weff<<<dim3(16, 16), 256>>>(rm, Wk, bk, Wk_hi, Wk_lo, bk_eff, 1.0f);
    f32_to_f16hl<<<E_DIM * E_DIM / 1024, 256>>>(Wv, Wv_hi, Wv_lo, E_DIM * E_DIM, 64.0f);
    f32_to_f16hl<<<E_DIM * E_DIM / 1024, 256>>>(Wo, Wo_hi, Wo_lo, E_DIM * E_DIM, 64.0f);

    dim3 gg(E_DIM / BN, TB / BM);   // (8, 128)
    const float inv = 1.0f / 16384.0f;   // undo x256 * W64
    // phi GEMMs: fp16 3-term (amplified path)
    tc_gemm<1, 0><<<gg, 256, SM_TOTAL>>>(x_hi, x_lo, Wq_hi, Wq_lo, bq_eff, phiq, inv, nullptr);
    tc_gemm<1, 0><<<gg, 256, SM_TOTAL>>>(x_hi, x_lo, Wk_hi, Wk_lo, bk_eff, phik, inv, nullptr);
    // v GEMM: 2-term drop B_lo
    tc_gemm<0, 1><<<gg, 256, SM_TOTAL>>>(x_hi, x_lo, Wv_hi, Wv_lo, bv, vbuf, inv, nullptr);

    // causal scan -> fp32 attn
    rfa_scan<<<B_DIM * H_DIM * 2, 256>>>(phiq, phik, vbuf, attn_f32);

    // per-row scale -> fp16 attn_hi + inv_s
    rowscale<<<TB / 8, 256>>>(attn_f32, attn_hi, inv_s);

    // out GEMM: 2-term drop A_lo; epilogue applies inv_s[row]/64
    tc_gemm<2, 2><<<gg, 256, SM_TOTAL>>>(attn_hi, attn_hi, Wo_hi, Wo_lo, bo, out,
                                         1.0f / 64.0f, inv_s);
}

// round 16
// speedup vs baseline: 1.1469x; 1.0400x over previous
#include <cuda_runtime.h>
#include <cuda_fp16.h>
#include <cstdint>

// ---------------------------------------------------------------------------
// CausalAttention (random-feature attention) — mma.sync split GEMMs.
// phi GEMMs: fp16 3-term, per-chunk RN drain — amplified path (unchanged).
// v GEMM:    fp16 2-term (drop B_lo), chain-128 (no drain), frag-hoisted.
// out GEMM:  fp16 2-term (drop A_lo) on row-scaled attn, chain-128, hoisted.
// Scan: d-split x2, 4 timesteps/iter; rowscale pass handles qz->EPS spikes.
// ---------------------------------------------------------------------------

#define T_DIM 2048
#define B_DIM 8
#define E_DIM 1024
#define H_DIM 16
#define TB    (T_DIM * B_DIM)          // 16384 rows
#define EPS_RFA 1e-6f

#define BM 128
#define BN 128
#define BK 32
#define NKT (E_DIM / BK)                // 32
#define ROW_B 80
#define ARR_B (128 * ROW_B)
#define STAGE_B (4 * ARR_B)             // 40960
#define NSTAGE 4
#define SM_BIAS 0
#define SM_STAGE0 1024
#define SM_TOTAL (SM_STAGE0 + NSTAGE * STAGE_B)   // 164864

#define SCAN_NS 4

// ------------------------- scratch (static device) -------------------------
__device__ __half g_x_hi[TB * E_DIM];
__device__ __half g_x_lo[TB * E_DIM];
__device__ __half g_Wq_hi[E_DIM * E_DIM];
__device__ __half g_Wq_lo[E_DIM * E_DIM];
__device__ __half g_Wk_hi[E_DIM * E_DIM];
__device__ __half g_Wk_lo[E_DIM * E_DIM];
__device__ __half g_Wv_hi[E_DIM * E_DIM];
__device__ __half g_Wv_lo[E_DIM * E_DIM];
__device__ __half g_Wo_hi[E_DIM * E_DIM];
__device__ __half g_Wo_lo[E_DIM * E_DIM];
__device__ float g_bq_eff[E_DIM];
__device__ float g_bk_eff[E_DIM];
__device__ float g_v   [TB * E_DIM];
__device__ float g_phiq[(size_t)TB * 2048];
__device__ float g_phik[(size_t)TB * 2048];
__device__ float g_attn_f32[TB * E_DIM];
__device__ __half g_attn_hi[TB * E_DIM];
__device__ float g_inv_s[TB];

// ----------------------------- PTX helpers ---------------------------------
__device__ __forceinline__ uint32_t smem_to_u32(const void* p) {
    uint32_t a;
    asm("{ .reg .u64 t; cvta.to.shared.u64 t, %1; cvt.u32.u64 %0, t; }" : "=r"(a) : "l"(p));
    return a;
}
__device__ __forceinline__ void cp16(uint32_t dst, const void* src) {
    asm volatile("cp.async.cg.shared.global [%0], [%1], 16;" :: "r"(dst), "l"(src) : "memory");
}
#define CP_COMMIT() asm volatile("cp.async.commit_group;" ::: "memory")
#define CP_WAIT2()  asm volatile("cp.async.wait_group 2;" ::: "memory")

__device__ __forceinline__ void ldsm4(uint32_t* r, uint32_t addr) {
    asm volatile("ldmatrix.sync.aligned.m8n8.x4.shared.b16 {%0,%1,%2,%3}, [%4];"
                 : "=r"(r[0]), "=r"(r[1]), "=r"(r[2]), "=r"(r[3]) : "r"(addr));
}
__device__ __forceinline__ void mma_f16(float* d, const uint32_t* a, const uint32_t* b) {
    asm volatile(
        "mma.sync.aligned.m16n8k16.row.col.f32.f16.f16.f32 "
        "{%0,%1,%2,%3}, {%4,%5,%6,%7}, {%8,%9}, {%0,%1,%2,%3};"
        : "+f"(d[0]), "+f"(d[1]), "+f"(d[2]), "+f"(d[3])
        : "r"(a[0]), "r"(a[1]), "r"(a[2]), "r"(a[3]), "r"(b[0]), "r"(b[1]));
}
__device__ __forceinline__ void mma_f16_zc(float* d, const uint32_t* a, const uint32_t* b) {
    asm volatile(
        "mma.sync.aligned.m16n8k16.row.col.f32.f16.f16.f32 "
        "{%0,%1,%2,%3}, {%4,%5,%6,%7}, {%8,%9}, {%10,%10,%10,%10};"
        : "=f"(d[0]), "=f"(d[1]), "=f"(d[2]), "=f"(d[3])
        : "r"(a[0]), "r"(a[1]), "r"(a[2]), "r"(a[3]), "r"(b[0]), "r"(b[1]),
          "f"(0.0f));
}

// ---------------------------------------------------------------------------
// fp32 -> fp16 hi/lo split (with pre-scale)
// ---------------------------------------------------------------------------
__global__ void __launch_bounds__(256) f32_to_f16hl(
    const float* __restrict__ in, __half* __restrict__ hi,
    __half* __restrict__ lo, int n, float scale)
{
    int i = (blockIdx.x * 256 + threadIdx.x) * 4;
    if (i >= n) return;
    float4 v = *(const float4*)(in + i);
    float a[4] = {v.x * scale, v.y * scale, v.z * scale, v.w * scale};
    __half h[4], l[4];
#pragma unroll
    for (int j = 0; j < 4; j++) {
        h[j] = __float2half_rn(a[j]);
        l[j] = __float2half_rn(a[j] - __half2float(h[j]));
    }
    *(__half2*)(hi + i)     = __halves2half2(h[0], h[1]);
    *(__half2*)(hi + i + 2) = __halves2half2(h[2], h[3]);
    *(__half2*)(lo + i)     = __halves2half2(l[0], l[1]);
    *(__half2*)(lo + i + 2) = __halves2half2(l[2], l[3]);
}

// ---------------------------------------------------------------------------
// Per-row dynamic scale of attn: one warp per (t,b) row of 1024 floats.
// ---------------------------------------------------------------------------
__global__ void __launch_bounds__(256) rowscale(
    const float* __restrict__ attn, __half* __restrict__ ahi,
    float* __restrict__ inv_s)
{
    const int row = blockIdx.x * 8 + (threadIdx.x >> 5);
    const int lane = threadIdx.x & 31;
    const float* src = attn + (size_t)row * E_DIM;
    float vals[32];
    float m = 0.f;
#pragma unroll
    for (int i = 0; i < 32; i++) {
        vals[i] = src[lane + i * 32];
        m = fmaxf(m, fabsf(vals[i]));
    }
#pragma unroll
    for (int off = 16; off; off >>= 1)
        m = fmaxf(m, __shfl_xor_sync(0xffffffffu, m, off));
    const float sr = 16384.f / fmaxf(m, 1.f);
    __half* dst = ahi + (size_t)row * E_DIM;
#pragma unroll
    for (int i = 0; i < 32; i++)
        dst[lane + i * 32] = __float2half_rn(vals[i] * sr);
    if (lane == 0) inv_s[row] = 1.f / sr;
}

// ---------------------------------------------------------------------------
// Weight prep: Weff[h*64+k, e] = scale * sum_d rm[h,k,d] * W[h*64+d, e]
// ---------------------------------------------------------------------------
__global__ void __launch_bounds__(256) prep_weff(
    const float* __restrict__ rm, const float* __restrict__ W,
    const float* __restrict__ bvec, __half* __restrict__ Whi,
    __half* __restrict__ Wlo, float* __restrict__ beff, float scale)
{
    const int h  = blockIdx.y;
    const int e0 = blockIdx.x * 64;
    const int tid = threadIdx.x;

    __shared__ float rs[64][65];
    __shared__ float ws[64][65];

    for (int i = tid; i < 4096; i += 256) {
        int k = i >> 6, dd = i & 63;
        rs[k][dd] = rm[h * 4096 + i];
    }
    for (int i = tid; i < 4096; i += 256) {
        int dd = i >> 6, e = i & 63;
        ws[dd][e] = W[(size_t)(h * 64 + dd) * E_DIM + e0 + e];
    }
    __syncthreads();

    const int tk = (tid >> 4) * 4;
    const int te = (tid & 15) * 4;
    float acc[4][4];
#pragma unroll
    for (int i = 0; i < 4; i++)
#pragma unroll
        for (int j = 0; j < 4; j++) acc[i][j] = 0.f;

#pragma unroll 8
    for (int dd = 0; dd < 64; dd++) {
        float a0 = rs[tk + 0][dd], a1 = rs[tk + 1][dd];
        float a2 = rs[tk + 2][dd], a3 = rs[tk + 3][dd];
        float b0 = ws[dd][te + 0], b1 = ws[dd][te + 1];
        float b2 = ws[dd][te + 2], b3 = ws[dd][te + 3];
        acc[0][0] += a0 * b0; acc[0][1] += a0 * b1; acc[0][2] += a0 * b2; acc[0][3] += a0 * b3;
        acc[1][0] += a1 * b0; acc[1][1] += a1 * b1; acc[1][2] += a1 * b2; acc[1][3] += a1 * b3;
        acc[2][0] += a2 * b0; acc[2][1] += a2 * b1; acc[2][2] += a2 * b2; acc[2][3] += a2 * b3;
        acc[3][0] += a3 * b0; acc[3][1] += a3 * b1; acc[3][2] += a3 * b2; acc[3][3] += a3 * b3;
    }
#pragma unroll
    for (int i = 0; i < 4; i++)
#pragma unroll
        for (int j = 0; j < 4; j++) {
            float val = 64.f * scale * acc[i][j];
            size_t idx = (size_t)(h * 64 + tk + i) * E_DIM + e0 + te + j;
            __half hv = __float2half_rn(val);
            Whi[idx] = hv;
            Wlo[idx] = __float2half_rn(val - __half2float(hv));
        }

    if (blockIdx.x == 0 && tid < 64) {
        float s = 0.f;
        for (int dd = 0; dd < 64; dd++) s += rs[tid][dd] * bvec[h * 64 + dd];
        beff[h * 64 + tid] = scale * s;
    }
}

// ---------------------------------------------------------------------------
// one k-stage loader — loads only the arrays the term-set uses
// ---------------------------------------------------------------------------
template <bool LA, bool LB>
__device__ __forceinline__ void load_stage(
    const __half* __restrict__ Ahi, const __half* __restrict__ Alo,
    const __half* __restrict__ Bhi, const __half* __restrict__ Blo,
    int m0, int n0, int kc0, uint32_t st, int tid)
{
#pragma unroll
    for (int i = 0; i < 2; i++) {
        const int idx = tid + 256 * i;
        const int row = idx >> 2;
        const int u = idx & 3;
        const uint32_t doff = row * ROW_B + u * 16;
        const size_t aoff = (size_t)(m0 + row) * E_DIM + kc0 + u * 8;
        const size_t boff = (size_t)(n0 + row) * E_DIM + kc0 + u * 8;
        cp16(st + doff, Ahi + aoff);
        if (LA) cp16(st + ARR_B + doff, Alo + aoff);
        cp16(st + 2 * ARR_B + doff, Bhi + boff);
        if (LB) cp16(st + 3 * ARR_B + doff, Blo + boff);
    }
}

// ---------------------------------------------------------------------------
// HMMA GEMM: split fp16, TMODE selects the term set:
//   TMODE 0: A_hi*B_hi + A_hi*B_lo + A_lo*B_hi   (3-term)
//   TMODE 1: A_hi*B_hi + A_lo*B_hi               (2-term, drop B_lo)
//   TMODE 2: A_hi*B_hi + A_hi*B_lo               (2-term, drop A_lo)
// MODE 1: per-chunk RN drain + phi epilogue (amplified path).
// MODE 0/2: NO drain (chain-128 in-HMMA; unamplified, bias ~8e-6) with
//           full-kt fragment hoisting; MODE 2 applies per-row rscale.
// ---------------------------------------------------------------------------
template <int MODE, int TMODE>
__global__ void __launch_bounds__(256, 1) tc_gemm(
    const __half* __restrict__ Ahi, const __half* __restrict__ Alo,
    const __half* __restrict__ Bhi, const __half* __restrict__ Blo,
    const float* __restrict__ bias, float* __restrict__ Cout, float escale,
    const float* __restrict__ rscale)
{
    extern __shared__ char smem[];
    const uint32_t sbase = smem_to_u32(smem);
    const int tid = threadIdx.x;
    const int wid = tid >> 5;
    const int lane = tid & 31;
    const int m0 = blockIdx.y * BM;
    const int n0 = blockIdx.x * BN;

    float* bias_s = (float*)(smem + SM_BIAS);
    if (tid < 128) bias_s[tid] = bias[n0 + tid];

    const int wm = wid >> 1;
    const int wn = wid & 1;
    const int g = lane >> 3;
    const int r = lane & 7;

    constexpr bool LA = (TMODE != 2);
    constexpr bool LB = (TMODE != 1);
    constexpr int NT = (TMODE == 0) ? 3 : 2;

#pragma unroll
    for (int s = 0; s < 3; s++) {
        load_stage<LA, LB>(Ahi, Alo, Bhi, Blo, m0, n0, s * BK,
                           sbase + SM_STAGE0 + s * STAGE_B, tid);
        CP_COMMIT();
    }

    float accm[2][8][4];
#pragma unroll
    for (int mt = 0; mt < 2; mt++)
#pragma unroll
        for (int j = 0; j < 8; j++)
#pragma unroll
            for (int c = 0; c < 4; c++) accm[mt][j][c] = 0.f;

    const uint32_t a_row_off = (uint32_t)((wm * 32 + (g & 1) * 8 + r) * ROW_B + (g >> 1) * 16);
    const uint32_t b_row_off = (uint32_t)((wn * 64 + (g >> 1) * 8 + r) * ROW_B + (g & 1) * 16);

    if (MODE == 1) {
        // ---------------- amplified path: accw + per-chunk RN drain --------
        float accw[2][8][4];
#pragma unroll 1
        for (int kt = 0; kt < NKT; kt++) {
            CP_WAIT2();
            __syncthreads();
            if (kt + 3 < NKT)
                load_stage<LA, LB>(Ahi, Alo, Bhi, Blo, m0, n0, (kt + 3) * BK,
                                   sbase + SM_STAGE0 + ((kt + 3) % NSTAGE) * STAGE_B, tid);
            CP_COMMIT();

            const uint32_t st = sbase + SM_STAGE0 + (kt % NSTAGE) * STAGE_B;
            const uint32_t sA[2] = { st, st + ARR_B };
            const uint32_t sB[2] = { st + 2 * ARR_B, st + 3 * ARR_B };

#pragma unroll
            for (int ks = 0; ks < 2; ks++) {
                uint32_t afr[2][2][4];
                uint32_t bfr[4][2][4];
#pragma unroll
                for (int mt = 0; mt < 2; mt++)
#pragma unroll
                    for (int hl = 0; hl < 2; hl++)
                        ldsm4(afr[mt][hl], sA[hl] + a_row_off + mt * (16 * ROW_B) + ks * 32);
#pragma unroll
                for (int jp = 0; jp < 4; jp++)
#pragma unroll
                    for (int hl = 0; hl < 2; hl++)
                        ldsm4(bfr[jp][hl], sB[hl] + b_row_off + jp * (16 * ROW_B) + ks * 32);

#pragma unroll
                for (int t = 0; t < 3; t++) {
                    const int pa = (t == 2) ? 1 : 0;   // hh, hl, lh
                    const int pb = (t == 1) ? 1 : 0;
                    const bool zc = (ks == 0 && t == 0);
#pragma unroll
                    for (int mt = 0; mt < 2; mt++)
#pragma unroll
                        for (int j = 0; j < 8; j++) {
                            const uint32_t* bj = &bfr[j >> 1][pb][(j & 1) * 2];
                            if (zc) mma_f16_zc(accw[mt][j], afr[mt][pa], bj);
                            else    mma_f16(accw[mt][j], afr[mt][pa], bj);
                        }
                }
            }
#pragma unroll
            for (int mt = 0; mt < 2; mt++)
#pragma unroll
                for (int j = 0; j < 8; j++)
#pragma unroll
                    for (int c = 0; c < 4; c++) accm[mt][j][c] += accw[mt][j][c];
        }
    } else {
        // -------- unamplified 2-term path: no drain, full-kt frag hoist ----
#pragma unroll 1
        for (int kt = 0; kt < NKT; kt++) {
            CP_WAIT2();
            __syncthreads();
            if (kt + 3 < NKT)
                load_stage<LA, LB>(Ahi, Alo, Bhi, Blo, m0, n0, (kt + 3) * BK,
                                   sbase + SM_STAGE0 + ((kt + 3) % NSTAGE) * STAGE_B, tid);
            CP_COMMIT();

            const uint32_t st = sbase + SM_STAGE0 + (kt % NSTAGE) * STAGE_B;
            const uint32_t sA[2] = { st, st + ARR_B };
            const uint32_t sB[2] = { st + 2 * ARR_B, st + 3 * ARR_B };

            // hoist ALL fragments for this kt (both ks halves)
            uint32_t afr[2][2][2][4];   // [ks][mt][pa][4] (pa slots used per TMODE)
            uint32_t bfr[2][4][2][4];   // [ks][jp][pb][4]
#pragma unroll
            for (int ks = 0; ks < 2; ks++) {
#pragma unroll
                for (int mt = 0; mt < 2; mt++)
#pragma unroll
                    for (int hl = 0; hl < (LA ? 2 : 1); hl++)
                        ldsm4(afr[ks][mt][hl], sA[hl] + a_row_off + mt * (16 * ROW_B) + ks * 32);
#pragma unroll
                for (int jp = 0; jp < 4; jp++)
#pragma unroll
                    for (int hl = 0; hl < (LB ? 2 : 1); hl++)
                        ldsm4(bfr[ks][jp][hl], sB[hl] + b_row_off + jp * (16 * ROW_B) + ks * 32);
            }
            // back-to-back MMA burst for the whole kt
#pragma unroll
            for (int ks = 0; ks < 2; ks++) {
#pragma unroll
                for (int t = 0; t < NT; t++) {
                    // TMODE 1: (hi,hi),(lo,hi).  TMODE 2: (hi,hi),(hi,lo)
                    const int pa = (TMODE == 1) ? t : 0;
                    const int pb = (TMODE == 1) ? 0 : t;
#pragma unroll
                    for (int mt = 0; mt < 2; mt++)
#pragma unroll
                        for (int j = 0; j < 8; j++) {
                            const uint32_t* bj = &bfr[ks][j >> 1][pb][(j & 1) * 2];
                            mma_f16(accm[mt][j], afr[ks][mt][pa], bj);
                        }
                }
            }
        }
    }

    // ------------------------------ epilogue --------------------------------
    const int qr = lane >> 2;
    const int qc = (lane & 3) * 2;
#pragma unroll
    for (int mt = 0; mt < 2; mt++) {
        const int row0 = m0 + wm * 32 + mt * 16 + qr;
        float es0 = escale, es1 = escale;
        if (MODE == 2) {
            es0 = escale * rscale[row0];
            es1 = escale * rscale[row0 + 8];
        }
#pragma unroll
        for (int j = 0; j < 8; j++) {
            const int coll = wn * 64 + j * 8 + qc;
            const int col = n0 + coll;
            const float b0 = bias_s[coll], b1 = bias_s[coll + 1];
            if (MODE != 1) {
                float2 v0 = make_float2(accm[mt][j][0] * es0 + b0,
                                        accm[mt][j][1] * es0 + b1);
                float2 v1 = make_float2(accm[mt][j][2] * es1 + b0,
                                        accm[mt][j][3] * es1 + b1);
                *(float2*)(Cout + (size_t)row0 * E_DIM + col) = v0;
                *(float2*)(Cout + (size_t)(row0 + 8) * E_DIM + col) = v1;
            } else {
                const int h = col >> 6, k = col & 63;
                float s0, c0s, s1, c1s, s2, c2s, s3, c3s;
                __sincosf(accm[mt][j][0] * escale + b0, &s0, &c0s);
                __sincosf(accm[mt][j][1] * escale + b1, &s1, &c1s);
                __sincosf(accm[mt][j][2] * escale + b0, &s2, &c2s);
                __sincosf(accm[mt][j][3] * escale + b1, &s3, &c3s);
                float* p0 = Cout + (size_t)row0 * 2048 + h * 128 + k;
                float* p1 = Cout + (size_t)(row0 + 8) * 2048 + h * 128 + k;
                p0[0] = s0 * 0.125f; p0[1]  = s1 * 0.125f;
                p0[64] = c0s * 0.125f; p0[65] = c1s * 0.125f;
                p1[0] = s2 * 0.125f; p1[1]  = s3 * 0.125f;
                p1[64] = c2s * 0.125f; p1[65] = c3s * 0.125f;
            }
        }
    }
}

// ---------------------------------------------------------------------------
// Causal RFA scan, d-split x2, SCAN_NS timesteps per iteration. fp32 attn out.
// ---------------------------------------------------------------------------
__global__ void __launch_bounds__(256) rfa_scan(
    const float* __restrict__ phiq, const float* __restrict__ phik,
    const float* __restrict__ v, float* __restrict__ attn)
{
    const int bx = blockIdx.x;
    const int dh = bx & 1;
    const int bh = bx >> 1;
    const int h = bh & 15;
    const int b = bh >> 4;
    const int tid = threadIdx.x;
    const int dl = tid & 31;
    const int kg = tid >> 5;

    __shared__ float s_pq[2][SCAN_NS][128], s_pk[2][SCAN_NS][128];
    __shared__ float s_v[2][SCAN_NS][32];
    __shared__ float s_z[128];
    __shared__ float s_red[SCAN_NS][256];
    __shared__ float s_qzp[SCAN_NS][4];

    float s_loc[16];
#pragma unroll
    for (int j = 0; j < 16; j++) s_loc[j] = 0.f;
    if (tid < 128) s_z[tid] = 0.f;

    const size_t phi_stride = (size_t)B_DIM * 2048;
    const size_t v_stride   = (size_t)B_DIM * 1024;
    const float* pq_base = phiq + (size_t)b * 2048 + h * 128;
    const float* pk_base = phik + (size_t)b * 2048 + h * 128;
    const float* v_base  = v    + (size_t)b * 1024 + h * 64 + dh * 32;
    const size_t o_off   = (size_t)b * 1024 + h * 64 + dh * 32;

    float ld_pq[SCAN_NS], ld_pk[SCAN_NS], ld_v[SCAN_NS];
#pragma unroll
    for (int s = 0; s < SCAN_NS; s++) { ld_pq[s] = 0.f; ld_pk[s] = 0.f; ld_v[s] = 0.f; }
    if (tid < 128) {
#pragma unroll
        for (int s = 0; s < SCAN_NS; s++) {
            ld_pq[s] = pq_base[(size_t)s * phi_stride + tid];
            ld_pk[s] = pk_base[(size_t)s * phi_stride + tid];
        }
    }
    if (tid < 32) {
#pragma unroll
        for (int s = 0; s < SCAN_NS; s++) ld_v[s] = v_base[(size_t)s * v_stride + tid];
    }
    int buf = 0;
    if (tid < 128) {
#pragma unroll
        for (int s = 0; s < SCAN_NS; s++) {
            s_pq[0][s][tid] = ld_pq[s];
            s_pk[0][s][tid] = ld_pk[s];
        }
    }
    if (tid < 32) {
#pragma unroll
        for (int s = 0; s < SCAN_NS; s++) s_v[0][s][tid] = ld_v[s];
    }
    __syncthreads();

    const int NGRP = T_DIM / SCAN_NS;
    for (int it = 0; it < NGRP; it++) {
        const size_t t0 = (size_t)(SCAN_NS * it);

        if (it + 1 < NGRP) {
            if (tid < 128) {
#pragma unroll
                for (int s = 0; s < SCAN_NS; s++) {
                    ld_pq[s] = pq_base[(t0 + SCAN_NS + s) * phi_stride + tid];
                    ld_pk[s] = pk_base[(t0 + SCAN_NS + s) * phi_stride + tid];
                }
            }
            if (tid < 32) {
#pragma unroll
                for (int s = 0; s < SCAN_NS; s++)
                    ld_v[s] = v_base[(t0 + SCAN_NS + s) * v_stride + tid];
            }
        }

        {
            float vd[SCAN_NS];
            const float *pkp[SCAN_NS], *pqp[SCAN_NS];
#pragma unroll
            for (int s = 0; s < SCAN_NS; s++) {
                vd[s] = s_v[buf][s][dl];
                pkp[s] = &s_pk[buf][s][kg * 16];
                pqp[s] = &s_pq[buf][s][kg * 16];
            }
            float acc[SCAN_NS][4];
#pragma unroll
            for (int s = 0; s < SCAN_NS; s++)
#pragma unroll
                for (int c = 0; c < 4; c++) acc[s][c] = 0.f;
#pragma unroll
            for (int j = 0; j < 16; j += 4) {
#pragma unroll
                for (int s = 0; s < SCAN_NS; s++) {
                    float4 kk = *(const float4*)(pkp[s] + j);
                    float4 qq = *(const float4*)(pqp[s] + j);
                    s_loc[j + 0] += kk.x * vd[s]; acc[s][0] += qq.x * s_loc[j + 0];
                    s_loc[j + 1] += kk.y * vd[s]; acc[s][1] += qq.y * s_loc[j + 1];
                    s_loc[j + 2] += kk.z * vd[s]; acc[s][2] += qq.z * s_loc[j + 2];
                    s_loc[j + 3] += kk.w * vd[s]; acc[s][3] += qq.w * s_loc[j + 3];
                }
            }
#pragma unroll
            for (int s = 0; s < SCAN_NS; s++)
                s_red[s][tid] = (acc[s][0] + acc[s][1]) + (acc[s][2] + acc[s][3]);
        }

        {
            float qzp[SCAN_NS];
#pragma unroll
            for (int s = 0; s < SCAN_NS; s++) qzp[s] = 0.f;
            if (tid < 128) {
                float z = s_z[tid];
#pragma unroll
                for (int s = 0; s < SCAN_NS; s++) {
                    z += s_pk[buf][s][tid];
                    qzp[s] = s_pq[buf][s][tid] * z;
                }
                s_z[tid] = z;
            }
#pragma unroll
            for (int off = 16; off; off >>= 1) {
#pragma unroll
                for (int s = 0; s < SCAN_NS; s++)
                    qzp[s] += __shfl_xor_sync(0xffffffffu, qzp[s], off);
            }
            if (tid < 128 && (tid & 31) == 0) {
#pragma unroll
                for (int s = 0; s < SCAN_NS; s++) s_qzp[s][tid >> 5] = qzp[s];
            }
        }
        __syncthreads();

        if (tid < 32) {
#pragma unroll
            for (int stp = 0; stp < SCAN_NS; stp++) {
                const float* rd = s_red[stp];
                float qs = ((rd[dl] + rd[32 + dl]) + (rd[64 + dl] + rd[96 + dl])) +
                           ((rd[128 + dl] + rd[160 + dl]) + (rd[192 + dl] + rd[224 + dl]));
                float qz = (s_qzp[stp][0] + s_qzp[stp][1]) +
                           (s_qzp[stp][2] + s_qzp[stp][3]);
                qz = fmaxf(qz, EPS_RFA);
                attn[(t0 + stp) * v_stride + o_off + dl] = qs / qz;
            }
        }

        buf ^= 1;
        if (it + 1 < NGRP) {
            if (tid < 128) {
#pragma unroll
                for (int s = 0; s < SCAN_NS; s++) {
                    s_pq[buf][s][tid] = ld_pq[s];
                    s_pk[buf][s][tid] = ld_pk[s];
                }
            }
            if (tid < 32) {
#pragma unroll
                for (int s = 0; s < SCAN_NS; s++) s_v[buf][s][tid] = ld_v[s];
            }
        }
        __syncthreads();
    }
}

// ---------------------------------------------------------------------------
extern "C" void kernel_launch(void* const* d_in, const int* in_sizes, int n_in,
                              void* d_out, int out_size)
{
    const float* x  = (const float*)d_in[0];
    const float* rm = (const float*)d_in[1];
    const float* Wq = (const float*)d_in[2];
    const float* bq = (const float*)d_in[3];
    const float* Wk = (const float*)d_in[4];
    const float* bk = (const float*)d_in[5];
    const float* Wv = (const float*)d_in[6];
    const float* bv = (const float*)d_in[7];
    const float* Wo = (const float*)d_in[8];
    const float* bo = (const float*)d_in[9];
    float* out = (float*)d_out;

    __half *x_hi, *x_lo, *Wq_hi, *Wq_lo, *Wk_hi, *Wk_lo, *Wv_hi, *Wv_lo,
           *Wo_hi, *Wo_lo, *attn_hi;
    float *bq_eff, *bk_eff, *vbuf, *phiq, *phik, *attn_f32, *inv_s;
    cudaGetSymbolAddress((void**)&x_hi, g_x_hi);
    cudaGetSymbolAddress((void**)&x_lo, g_x_lo);
    cudaGetSymbolAddress((void**)&Wq_hi, g_Wq_hi);
    cudaGetSymbolAddress((void**)&Wq_lo, g_Wq_lo);
    cudaGetSymbolAddress((void**)&Wk_hi, g_Wk_hi);
    cudaGetSymbolAddress((void**)&Wk_lo, g_Wk_lo);
    cudaGetSymbolAddress((void**)&Wv_hi, g_Wv_hi);
    cudaGetSymbolAddress((void**)&Wv_lo, g_Wv_lo);
    cudaGetSymbolAddress((void**)&Wo_hi, g_Wo_hi);
    cudaGetSymbolAddress((void**)&Wo_lo, g_Wo_lo);
    cudaGetSymbolAddress((void**)&attn_hi, g_attn_hi);
    cudaGetSymbolAddress((void**)&attn_f32, g_attn_f32);
    cudaGetSymbolAddress((void**)&inv_s, g_inv_s);
    cudaGetSymbolAddress((void**)&bq_eff, g_bq_eff);
    cudaGetSymbolAddress((void**)&bk_eff, g_bk_eff);
    cudaGetSymbolAddress((void**)&vbuf, g_v);
    cudaGetSymbolAddress((void**)&phiq, g_phiq);
    cudaGetSymbolAddress((void**)&phik, g_phik);

    cudaFuncSetAttribute((const void*)tc_gemm<1, 0>,
                         cudaFuncAttributeMaxDynamicSharedMemorySize, SM_TOTAL);
    cudaFuncSetAttribute((const void*)tc_gemm<0, 1>,
                         cudaFuncAttributeMaxDynamicSharedMemorySize, SM_TOTAL);
    cudaFuncSetAttribute((const void*)tc_gemm<2, 2>,
                         cudaFuncAttributeMaxDynamicSharedMemorySize, SM_TOTAL);

    // conversions + weight prep: x scaled x256, weights x64 (fp16 lo range).
    f32_to_f16hl<<<TB * E_DIM / 1024, 256>>>(x, x_hi, x_lo, TB * E_DIM, 256.0f);
    prep_weff<<<dim3(16, 16), 256>>>(rm, Wq, bq, Wq_hi, Wq_lo, bq_eff, 0.125f);
    prep_weff<<<dim3(16, 16), 256>>>(rm, Wk, bk, Wk_hi, Wk_lo, bk_eff, 1.0f);
    f32_to_f16hl<<<E_DIM * E_DIM / 1024, 256>>>(Wv, Wv_hi, Wv_lo, E_DIM * E_DIM, 64.0f);
    f32_to_f16hl<<<E_DIM * E_DIM / 1024, 256>>>(Wo, Wo_hi, Wo_lo, E_DIM * E_DIM, 64.0f);

    dim3 gg(E_DIM / BN, TB / BM);   // (8, 128)
    const float inv = 1.0f / 16384.0f;   // undo x256 * W64
    // phi GEMMs: fp16 3-term with RN drain (amplified path)
    tc_gemm<1, 0><<<gg, 256, SM_TOTAL>>>(x_hi, x_lo, Wq_hi, Wq_lo, bq_eff, phiq, inv, nullptr);
    tc_gemm<1, 0><<<gg, 256, SM_TOTAL>>>(x_hi, x_lo, Wk_hi, Wk_lo, bk_eff, phik, inv, nullptr);
    // v GEMM: 2-term drop B_lo, chain-128, frag-hoisted
    tc_gemm<0, 1><<<gg, 256, SM_TOTAL>>>(x_hi, x_lo, Wv_hi, Wv_lo, bv, vbuf, inv, nullptr);

    // causal scan -> fp32 attn
    rfa_scan<<<B_DIM * H_DIM * 2, 256>>>(phiq, phik, vbuf, attn_f32);

    // per-row scale -> fp16 attn_hi + inv_s
    rowscale<<<TB / 8, 256>>>(attn_f32, attn_hi, inv_s);

    // out GEMM: 2-term drop A_lo, chain-128, frag-hoisted; inv_s[row]/64
    tc_gemm<2, 2><<<gg, 256, SM_TOTAL>>>(attn_hi, attn_hi, Wo_hi, Wo_lo, bo, out,
                                         1.0f / 64.0f, inv_s);
}

// round 17
// speedup vs baseline: 1.1873x; 1.0352x over previous
#include <cuda_runtime.h>
#include <cuda_fp16.h>
#include <cstdint>

// ---------------------------------------------------------------------------
// CausalAttention (random-feature attention) — mma.sync split GEMMs.
// phi GEMMs: fp16 3-term, per-chunk RN drain, 4-array 4-stage, 1 CTA/SM.
// v GEMM:    fp16 2-term (drop B_lo), chain-128, 3-array 3-stage, 2 CTA/SM.
// out GEMM:  fp16 2-term (drop A_lo), row-scaled attn, 3-array, 2 CTA/SM.
// Scan: d-split x2, 4 timesteps/iter; rowscale handles qz->EPS spikes.
// ---------------------------------------------------------------------------

#define T_DIM 2048
#define B_DIM 8
#define E_DIM 1024
#define H_DIM 16
#define TB    (T_DIM * B_DIM)          // 16384 rows
#define EPS_RFA 1e-6f

#define BM 128
#define BN 128
#define BK 32
#define NKT (E_DIM / BK)                // 32
#define ROW_B 80
#define ARR_B (128 * ROW_B)             // 10240
// 4-array (phi) config: 4 stages
#define STAGE4_B (4 * ARR_B)            // 40960
#define SM4_TOTAL (1024 + 4 * STAGE4_B) // 164864
// 3-array (2-term) config: 3 stages, 2 CTAs/SM
#define STAGE3_B (3 * ARR_B)            // 30720
#define SM3_TOTAL (1024 + 3 * STAGE3_B) // 93184
#define SM_BIAS 0
#define SM_STAGE0 1024

#define SCAN_NS 4

// ------------------------- scratch (static device) -------------------------
__device__ __half g_x_hi[TB * E_DIM];
__device__ __half g_x_lo[TB * E_DIM];
__device__ __half g_Wq_hi[E_DIM * E_DIM];
__device__ __half g_Wq_lo[E_DIM * E_DIM];
__device__ __half g_Wk_hi[E_DIM * E_DIM];
__device__ __half g_Wk_lo[E_DIM * E_DIM];
__device__ __half g_Wv_hi[E_DIM * E_DIM];
__device__ __half g_Wo_hi[E_DIM * E_DIM];
__device__ __half g_Wo_lo[E_DIM * E_DIM];
__device__ float g_bq_eff[E_DIM];
__device__ float g_bk_eff[E_DIM];
__device__ float g_v   [TB * E_DIM];
__device__ float g_phiq[(size_t)TB * 2048];
__device__ float g_phik[(size_t)TB * 2048];
__device__ float g_attn_f32[TB * E_DIM];
__device__ __half g_attn_hi[TB * E_DIM];
__device__ float g_inv_s[TB];

// ----------------------------- PTX helpers ---------------------------------
__device__ __forceinline__ uint32_t smem_to_u32(const void* p) {
    uint32_t a;
    asm("{ .reg .u64 t; cvta.to.shared.u64 t, %1; cvt.u32.u64 %0, t; }" : "=r"(a) : "l"(p));
    return a;
}
__device__ __forceinline__ void cp16(uint32_t dst, const void* src) {
    asm volatile("cp.async.cg.shared.global [%0], [%1], 16;" :: "r"(dst), "l"(src) : "memory");
}
#define CP_COMMIT() asm volatile("cp.async.commit_group;" ::: "memory")
#define CP_WAIT2()  asm volatile("cp.async.wait_group 2;" ::: "memory")
#define CP_WAIT1()  asm volatile("cp.async.wait_group 1;" ::: "memory")

__device__ __forceinline__ void ldsm4(uint32_t* r, uint32_t addr) {
    asm volatile("ldmatrix.sync.aligned.m8n8.x4.shared.b16 {%0,%1,%2,%3}, [%4];"
                 : "=r"(r[0]), "=r"(r[1]), "=r"(r[2]), "=r"(r[3]) : "r"(addr));
}
__device__ __forceinline__ void mma_f16(float* d, const uint32_t* a, const uint32_t* b) {
    asm volatile(
        "mma.sync.aligned.m16n8k16.row.col.f32.f16.f16.f32 "
        "{%0,%1,%2,%3}, {%4,%5,%6,%7}, {%8,%9}, {%0,%1,%2,%3};"
        : "+f"(d[0]), "+f"(d[1]), "+f"(d[2]), "+f"(d[3])
        : "r"(a[0]), "r"(a[1]), "r"(a[2]), "r"(a[3]), "r"(b[0]), "r"(b[1]));
}
__device__ __forceinline__ void mma_f16_zc(float* d, const uint32_t* a, const uint32_t* b) {
    asm volatile(
        "mma.sync.aligned.m16n8k16.row.col.f32.f16.f16.f32 "
        "{%0,%1,%2,%3}, {%4,%5,%6,%7}, {%8,%9}, {%10,%10,%10,%10};"
        : "=f"(d[0]), "=f"(d[1]), "=f"(d[2]), "=f"(d[3])
        : "r"(a[0]), "r"(a[1]), "r"(a[2]), "r"(a[3]), "r"(b[0]), "r"(b[1]),
          "f"(0.0f));
}

// ---------------------------------------------------------------------------
// fp32 -> fp16 hi/lo split (with pre-scale)
// ---------------------------------------------------------------------------
__global__ void __launch_bounds__(256) f32_to_f16hl(
    const float* __restrict__ in, __half* __restrict__ hi,
    __half* __restrict__ lo, int n, float scale)
{
    int i = (blockIdx.x * 256 + threadIdx.x) * 4;
    if (i >= n) return;
    float4 v = *(const float4*)(in + i);
    float a[4] = {v.x * scale, v.y * scale, v.z * scale, v.w * scale};
    __half h[4], l[4];
#pragma unroll
    for (int j = 0; j < 4; j++) {
        h[j] = __float2half_rn(a[j]);
        l[j] = __float2half_rn(a[j] - __half2float(h[j]));
    }
    *(__half2*)(hi + i)     = __halves2half2(h[0], h[1]);
    *(__half2*)(hi + i + 2) = __halves2half2(h[2], h[3]);
    if (lo) {
        *(__half2*)(lo + i)     = __halves2half2(l[0], l[1]);
        *(__half2*)(lo + i + 2) = __halves2half2(l[2], l[3]);
    }
}

// ---------------------------------------------------------------------------
// Per-row dynamic scale of attn: one warp per (t,b) row of 1024 floats.
// ---------------------------------------------------------------------------
__global__ void __launch_bounds__(256) rowscale(
    const float* __restrict__ attn, __half* __restrict__ ahi,
    float* __restrict__ inv_s)
{
    const int row = blockIdx.x * 8 + (threadIdx.x >> 5);
    const int lane = threadIdx.x & 31;
    const float* src = attn + (size_t)row * E_DIM;
    float vals[32];
    float m = 0.f;
#pragma unroll
    for (int i = 0; i < 32; i++) {
        vals[i] = src[lane + i * 32];
        m = fmaxf(m, fabsf(vals[i]));
    }
#pragma unroll
    for (int off = 16; off; off >>= 1)
        m = fmaxf(m, __shfl_xor_sync(0xffffffffu, m, off));
    const float sr = 16384.f / fmaxf(m, 1.f);
    __half* dst = ahi + (size_t)row * E_DIM;
#pragma unroll
    for (int i = 0; i < 32; i++)
        dst[lane + i * 32] = __float2half_rn(vals[i] * sr);
    if (lane == 0) inv_s[row] = 1.f / sr;
}

// ---------------------------------------------------------------------------
// Weight prep: Weff[h*64+k, e] = scale * sum_d rm[h,k,d] * W[h*64+d, e]
// ---------------------------------------------------------------------------
__global__ void __launch_bounds__(256) prep_weff(
    const float* __restrict__ rm, const float* __restrict__ W,
    const float* __restrict__ bvec, __half* __restrict__ Whi,
    __half* __restrict__ Wlo, float* __restrict__ beff, float scale)
{
    const int h  = blockIdx.y;
    const int e0 = blockIdx.x * 64;
    const int tid = threadIdx.x;

    __shared__ float rs[64][65];
    __shared__ float ws[64][65];

    for (int i = tid; i < 4096; i += 256) {
        int k = i >> 6, dd = i & 63;
        rs[k][dd] = rm[h * 4096 + i];
    }
    for (int i = tid; i < 4096; i += 256) {
        int dd = i >> 6, e = i & 63;
        ws[dd][e] = W[(size_t)(h * 64 + dd) * E_DIM + e0 + e];
    }
    __syncthreads();

    const int tk = (tid >> 4) * 4;
    const int te = (tid & 15) * 4;
    float acc[4][4];
#pragma unroll
    for (int i = 0; i < 4; i++)
#pragma unroll
        for (int j = 0; j < 4; j++) acc[i][j] = 0.f;

#pragma unroll 8
    for (int dd = 0; dd < 64; dd++) {
        float a0 = rs[tk + 0][dd], a1 = rs[tk + 1][dd];
        float a2 = rs[tk + 2][dd], a3 = rs[tk + 3][dd];
        float b0 = ws[dd][te + 0], b1 = ws[dd][te + 1];
        float b2 = ws[dd][te + 2], b3 = ws[dd][te + 3];
        acc[0][0] += a0 * b0; acc[0][1] += a0 * b1; acc[0][2] += a0 * b2; acc[0][3] += a0 * b3;
        acc[1][0] += a1 * b0; acc[1][1] += a1 * b1; acc[1][2] += a1 * b2; acc[1][3] += a1 * b3;
        acc[2][0] += a2 * b0; acc[2][1] += a2 * b1; acc[2][2] += a2 * b2; acc[2][3] += a2 * b3;
        acc[3][0] += a3 * b0; acc[3][1] += a3 * b1; acc[3][2] += a3 * b2; acc[3][3] += a3 * b3;
    }
#pragma unroll
    for (int i = 0; i < 4; i++)
#pragma unroll
        for (int j = 0; j < 4; j++) {
            float val = 64.f * scale * acc[i][j];
            size_t idx = (size_t)(h * 64 + tk + i) * E_DIM + e0 + te + j;
            __half hv = __float2half_rn(val);
            Whi[idx] = hv;
            Wlo[idx] = __float2half_rn(val - __half2float(hv));
        }

    if (blockIdx.x == 0 && tid < 64) {
        float s = 0.f;
        for (int dd = 0; dd < 64; dd++) s += rs[tid][dd] * bvec[h * 64 + dd];
        beff[h * 64 + tid] = scale * s;
    }
}

// ---------------------------------------------------------------------------
// 4-array stage loader (phi GEMMs): [Ahi, Alo, Bhi, Blo]
// ---------------------------------------------------------------------------
__device__ __forceinline__ void load_stage4(
    const __half* __restrict__ Ahi, const __half* __restrict__ Alo,
    const __half* __restrict__ Bhi, const __half* __restrict__ Blo,
    int m0, int n0, int kc0, uint32_t st, int tid)
{
#pragma unroll
    for (int i = 0; i < 2; i++) {
        const int idx = tid + 256 * i;
        const int row = idx >> 2;
        const int u = idx & 3;
        const uint32_t doff = row * ROW_B + u * 16;
        const size_t aoff = (size_t)(m0 + row) * E_DIM + kc0 + u * 8;
        const size_t boff = (size_t)(n0 + row) * E_DIM + kc0 + u * 8;
        cp16(st + doff,             Ahi + aoff);
        cp16(st + ARR_B + doff,     Alo + aoff);
        cp16(st + 2 * ARR_B + doff, Bhi + boff);
        cp16(st + 3 * ARR_B + doff, Blo + boff);
    }
}

// 3-array stage loader (2-term GEMMs): [P0(A), P1, P2]; P1_IS_A selects m0/n0.
template <bool P1_IS_A>
__device__ __forceinline__ void load_stage3(
    const __half* __restrict__ P0, const __half* __restrict__ P1,
    const __half* __restrict__ P2,
    int m0, int n0, int kc0, uint32_t st, int tid)
{
#pragma unroll
    for (int i = 0; i < 2; i++) {
        const int idx = tid + 256 * i;
        const int row = idx >> 2;
        const int u = idx & 3;
        const uint32_t doff = row * ROW_B + u * 16;
        const size_t aoff = (size_t)(m0 + row) * E_DIM + kc0 + u * 8;
        const size_t boff = (size_t)(n0 + row) * E_DIM + kc0 + u * 8;
        cp16(st + doff, P0 + aoff);
        cp16(st + ARR_B + doff, P1 + (P1_IS_A ? aoff : boff));
        cp16(st + 2 * ARR_B + doff, P2 + boff);
    }
}

// ---------------------------------------------------------------------------
// phi GEMM (MODE 1): fp16 3-term, per-chunk RN drain, sincos epilogue.
// 4-array smem, 4-stage ring, 1 CTA/SM.
// ---------------------------------------------------------------------------
__global__ void __launch_bounds__(256, 1) tc_gemm_phi(
    const __half* __restrict__ Ahi, const __half* __restrict__ Alo,
    const __half* __restrict__ Bhi, const __half* __restrict__ Blo,
    const float* __restrict__ bias, float* __restrict__ Cout, float escale)
{
    extern __shared__ char smem[];
    const uint32_t sbase = smem_to_u32(smem);
    const int tid = threadIdx.x;
    const int wid = tid >> 5;
    const int lane = tid & 31;
    const int m0 = blockIdx.y * BM;
    const int n0 = blockIdx.x * BN;

    float* bias_s = (float*)(smem + SM_BIAS);
    if (tid < 128) bias_s[tid] = bias[n0 + tid];

    const int wm = wid >> 1;
    const int wn = wid & 1;
    const int g = lane >> 3;
    const int r = lane & 7;

#pragma unroll
    for (int s = 0; s < 3; s++) {
        load_stage4(Ahi, Alo, Bhi, Blo, m0, n0, s * BK,
                    sbase + SM_STAGE0 + s * STAGE4_B, tid);
        CP_COMMIT();
    }

    float accm[2][8][4];
    float accw[2][8][4];
#pragma unroll
    for (int mt = 0; mt < 2; mt++)
#pragma unroll
        for (int j = 0; j < 8; j++)
#pragma unroll
            for (int c = 0; c < 4; c++) accm[mt][j][c] = 0.f;

    const uint32_t a_row_off = (uint32_t)((wm * 32 + (g & 1) * 8 + r) * ROW_B + (g >> 1) * 16);
    const uint32_t b_row_off = (uint32_t)((wn * 64 + (g >> 1) * 8 + r) * ROW_B + (g & 1) * 16);

#pragma unroll 1
    for (int kt = 0; kt < NKT; kt++) {
        CP_WAIT2();
        __syncthreads();
        if (kt + 3 < NKT)
            load_stage4(Ahi, Alo, Bhi, Blo, m0, n0, (kt + 3) * BK,
                        sbase + SM_STAGE0 + ((kt + 3) % 4) * STAGE4_B, tid);
        CP_COMMIT();

        const uint32_t st = sbase + SM_STAGE0 + (kt % 4) * STAGE4_B;
        const uint32_t sA[2] = { st, st + ARR_B };
        const uint32_t sB[2] = { st + 2 * ARR_B, st + 3 * ARR_B };

#pragma unroll
        for (int ks = 0; ks < 2; ks++) {
            uint32_t afr[2][2][4];
            uint32_t bfr[4][2][4];
#pragma unroll
            for (int mt = 0; mt < 2; mt++)
#pragma unroll
                for (int hl = 0; hl < 2; hl++)
                    ldsm4(afr[mt][hl], sA[hl] + a_row_off + mt * (16 * ROW_B) + ks * 32);
#pragma unroll
            for (int jp = 0; jp < 4; jp++)
#pragma unroll
                for (int hl = 0; hl < 2; hl++)
                    ldsm4(bfr[jp][hl], sB[hl] + b_row_off + jp * (16 * ROW_B) + ks * 32);

#pragma unroll
            for (int t = 0; t < 3; t++) {
                const int pa = (t == 2) ? 1 : 0;   // hh, hl, lh
                const int pb = (t == 1) ? 1 : 0;
                const bool zc = (ks == 0 && t == 0);
#pragma unroll
                for (int mt = 0; mt < 2; mt++)
#pragma unroll
                    for (int j = 0; j < 8; j++) {
                        const uint32_t* bj = &bfr[j >> 1][pb][(j & 1) * 2];
                        if (zc) mma_f16_zc(accw[mt][j], afr[mt][pa], bj);
                        else    mma_f16(accw[mt][j], afr[mt][pa], bj);
                    }
            }
        }
#pragma unroll
        for (int mt = 0; mt < 2; mt++)
#pragma unroll
            for (int j = 0; j < 8; j++)
#pragma unroll
                for (int c = 0; c < 4; c++) accm[mt][j][c] += accw[mt][j][c];
    }

    // phi epilogue
    const int qr = lane >> 2;
    const int qc = (lane & 3) * 2;
#pragma unroll
    for (int mt = 0; mt < 2; mt++) {
        const int row0 = m0 + wm * 32 + mt * 16 + qr;
#pragma unroll
        for (int j = 0; j < 8; j++) {
            const int coll = wn * 64 + j * 8 + qc;
            const int col = n0 + coll;
            const float b0 = bias_s[coll], b1 = bias_s[coll + 1];
            const int h = col >> 6, k = col & 63;
            float s0, c0s, s1, c1s, s2, c2s, s3, c3s;
            __sincosf(accm[mt][j][0] * escale + b0, &s0, &c0s);
            __sincosf(accm[mt][j][1] * escale + b1, &s1, &c1s);
            __sincosf(accm[mt][j][2] * escale + b0, &s2, &c2s);
            __sincosf(accm[mt][j][3] * escale + b1, &s3, &c3s);
            float* p0 = Cout + (size_t)row0 * 2048 + h * 128 + k;
            float* p1 = Cout + (size_t)(row0 + 8) * 2048 + h * 128 + k;
            p0[0] = s0 * 0.125f; p0[1]  = s1 * 0.125f;
            p0[64] = c0s * 0.125f; p0[65] = c1s * 0.125f;
            p1[0] = s2 * 0.125f; p1[1]  = s3 * 0.125f;
            p1[64] = c2s * 0.125f; p1[65] = c3s * 0.125f;
        }
    }
}

// ---------------------------------------------------------------------------
// 2-term GEMM (v / out): chain-128 (no drain), 3-array smem, 3-stage ring,
// 2 CTAs/SM. TMODE 1: terms (Ahi,Bhi)+(Alo,Bhi), slots [Ahi,Alo,Bhi].
//            TMODE 2: terms (Ahi,Bhi)+(Ahi,Blo), slots [Ahi,Bhi,Blo].
// rscale != nullptr applies per-row scale in the epilogue.
// ---------------------------------------------------------------------------
template <int TMODE>
__global__ void __launch_bounds__(256, 2) tc_gemm2(
    const __half* __restrict__ P0, const __half* __restrict__ P1,
    const __half* __restrict__ P2,
    const float* __restrict__ bias, float* __restrict__ Cout, float escale,
    const float* __restrict__ rscale)
{
    extern __shared__ char smem[];
    const uint32_t sbase = smem_to_u32(smem);
    const int tid = threadIdx.x;
    const int wid = tid >> 5;
    const int lane = tid & 31;
    const int m0 = blockIdx.y * BM;
    const int n0 = blockIdx.x * BN;

    float* bias_s = (float*)(smem + SM_BIAS);
    if (tid < 128) bias_s[tid] = bias[n0 + tid];

    const int wm = wid >> 1;
    const int wn = wid & 1;
    const int g = lane >> 3;
    const int r = lane & 7;

    constexpr bool P1A = (TMODE == 1);

    load_stage3<P1A>(P0, P1, P2, m0, n0, 0,  sbase + SM_STAGE0, tid);
    CP_COMMIT();
    load_stage3<P1A>(P0, P1, P2, m0, n0, BK, sbase + SM_STAGE0 + STAGE3_B, tid);
    CP_COMMIT();

    float accm[2][8][4];
#pragma unroll
    for (int mt = 0; mt < 2; mt++)
#pragma unroll
        for (int j = 0; j < 8; j++)
#pragma unroll
            for (int c = 0; c < 4; c++) accm[mt][j][c] = 0.f;

    const uint32_t a_row_off = (uint32_t)((wm * 32 + (g & 1) * 8 + r) * ROW_B + (g >> 1) * 16);
    const uint32_t b_row_off = (uint32_t)((wn * 64 + (g >> 1) * 8 + r) * ROW_B + (g & 1) * 16);

#pragma unroll 1
    for (int kt = 0; kt < NKT; kt++) {
        CP_WAIT1();        // slot kt%3 ready
        __syncthreads();   // readers of slot (kt+2)%3 == (kt-1)%3 done

        if (kt + 2 < NKT)
            load_stage3<P1A>(P0, P1, P2, m0, n0, (kt + 2) * BK,
                             sbase + SM_STAGE0 + ((kt + 2) % 3) * STAGE3_B, tid);
        CP_COMMIT();

        const uint32_t st = sbase + SM_STAGE0 + (kt % 3) * STAGE3_B;
        // TMODE1: sA = {slot0, slot1}, sB = {slot2}
        // TMODE2: sA = {slot0},        sB = {slot1, slot2}
        const uint32_t sA0 = st;
        const uint32_t sA1 = st + ARR_B;                    // TMODE1 only
        const uint32_t sB0 = (TMODE == 1) ? st + 2 * ARR_B : st + ARR_B;
        const uint32_t sB1 = st + 2 * ARR_B;                // TMODE2 only

#pragma unroll
        for (int ks = 0; ks < 2; ks++) {
            uint32_t afr[2][2][4];   // [mt][pa]
            uint32_t bfr[4][2][4];   // [jp][pb]
#pragma unroll
            for (int mt = 0; mt < 2; mt++) {
                ldsm4(afr[mt][0], sA0 + a_row_off + mt * (16 * ROW_B) + ks * 32);
                if (TMODE == 1)
                    ldsm4(afr[mt][1], sA1 + a_row_off + mt * (16 * ROW_B) + ks * 32);
            }
#pragma unroll
            for (int jp = 0; jp < 4; jp++) {
                ldsm4(bfr[jp][0], sB0 + b_row_off + jp * (16 * ROW_B) + ks * 32);
                if (TMODE == 2)
                    ldsm4(bfr[jp][1], sB1 + b_row_off + jp * (16 * ROW_B) + ks * 32);
            }
#pragma unroll
            for (int t = 0; t < 2; t++) {
                const int pa = (TMODE == 1) ? t : 0;
                const int pb = (TMODE == 1) ? 0 : t;
#pragma unroll
                for (int mt = 0; mt < 2; mt++)
#pragma unroll
                    for (int j = 0; j < 8; j++) {
                        const uint32_t* bj = &bfr[j >> 1][pb][(j & 1) * 2];
                        mma_f16(accm[mt][j], afr[mt][pa], bj);
                    }
            }
        }
    }

    // plain / row-scaled epilogue
    const int qr = lane >> 2;
    const int qc = (lane & 3) * 2;
#pragma unroll
    for (int mt = 0; mt < 2; mt++) {
        const int row0 = m0 + wm * 32 + mt * 16 + qr;
        float es0 = escale, es1 = escale;
        if (rscale) {
            es0 = escale * rscale[row0];
            es1 = escale * rscale[row0 + 8];
        }
#pragma unroll
        for (int j = 0; j < 8; j++) {
            const int coll = wn * 64 + j * 8 + qc;
            const int col = n0 + coll;
            const float b0 = bias_s[coll], b1 = bias_s[coll + 1];
            float2 v0 = make_float2(accm[mt][j][0] * es0 + b0,
                                    accm[mt][j][1] * es0 + b1);
            float2 v1 = make_float2(accm[mt][j][2] * es1 + b0,
                                    accm[mt][j][3] * es1 + b1);
            *(float2*)(Cout + (size_t)row0 * E_DIM + col) = v0;
            *(float2*)(Cout + (size_t)(row0 + 8) * E_DIM + col) = v1;
        }
    }
}

// ---------------------------------------------------------------------------
// Causal RFA scan, d-split x2, SCAN_NS timesteps per iteration. fp32 attn out.
// ---------------------------------------------------------------------------
__global__ void __launch_bounds__(256) rfa_scan(
    const float* __restrict__ phiq, const float* __restrict__ phik,
    const float* __restrict__ v, float* __restrict__ attn)
{
    const int bx = blockIdx.x;
    const int dh = bx & 1;
    const int bh = bx >> 1;
    const int h = bh & 15;
    const int b = bh >> 4;
    const int tid = threadIdx.x;
    const int dl = tid & 31;
    const int kg = tid >> 5;

    __shared__ float s_pq[2][SCAN_NS][128], s_pk[2][SCAN_NS][128];
    __shared__ float s_v[2][SCAN_NS][32];
    __shared__ float s_z[128];
    __shared__ float s_red[SCAN_NS][256];
    __shared__ float s_qzp[SCAN_NS][4];

    float s_loc[16];
#pragma unroll
    for (int j = 0; j < 16; j++) s_loc[j] = 0.f;
    if (tid < 128) s_z[tid] = 0.f;

    const size_t phi_stride = (size_t)B_DIM * 2048;
    const size_t v_stride   = (size_t)B_DIM * 1024;
    const float* pq_base = phiq + (size_t)b * 2048 + h * 128;
    const float* pk_base = phik + (size_t)b * 2048 + h * 128;
    const float* v_base  = v    + (size_t)b * 1024 + h * 64 + dh * 32;
    const size_t o_off   = (size_t)b * 1024 + h * 64 + dh * 32;

    float ld_pq[SCAN_NS], ld_pk[SCAN_NS], ld_v[SCAN_NS];
#pragma unroll
    for (int s = 0; s < SCAN_NS; s++) { ld_pq[s] = 0.f; ld_pk[s] = 0.f; ld_v[s] = 0.f; }
    if (tid < 128) {
#pragma unroll
        for (int s = 0; s < SCAN_NS; s++) {
            ld_pq[s] = pq_base[(size_t)s * phi_stride + tid];
            ld_pk[s] = pk_base[(size_t)s * phi_stride + tid];
        }
    }
    if (tid < 32) {
#pragma unroll
        for (int s = 0; s < SCAN_NS; s++) ld_v[s] = v_base[(size_t)s * v_stride + tid];
    }
    int buf = 0;
    if (tid < 128) {
#pragma unroll
        for (int s = 0; s < SCAN_NS; s++) {
            s_pq[0][s][tid] = ld_pq[s];
            s_pk[0][s][tid] = ld_pk[s];
        }
    }
    if (tid < 32) {
#pragma unroll
        for (int s = 0; s < SCAN_NS; s++) s_v[0][s][tid] = ld_v[s];
    }
    __syncthreads();

    const int NGRP = T_DIM / SCAN_NS;
    for (int it = 0; it < NGRP; it++) {
        const size_t t0 = (size_t)(SCAN_NS * it);

        if (it + 1 < NGRP) {
            if (tid < 128) {
#pragma unroll
                for (int s = 0; s < SCAN_NS; s++) {
                    ld_pq[s] = pq_base[(t0 + SCAN_NS + s) * phi_stride + tid];
                    ld_pk[s] = pk_base[(t0 + SCAN_NS + s) * phi_stride + tid];
                }
            }
            if (tid < 32) {
#pragma unroll
                for (int s = 0; s < SCAN_NS; s++)
                    ld_v[s] = v_base[(t0 + SCAN_NS + s) * v_stride + tid];
            }
        }

        {
            float vd[SCAN_NS];
            const float *pkp[SCAN_NS], *pqp[SCAN_NS];
#pragma unroll
            for (int s = 0; s < SCAN_NS; s++) {
                vd[s] = s_v[buf][s][dl];
                pkp[s] = &s_pk[buf][s][kg * 16];
                pqp[s] = &s_pq[buf][s][kg * 16];
            }
            float acc[SCAN_NS][4];
#pragma unroll
            for (int s = 0; s < SCAN_NS; s++)
#pragma unroll
                for (int c = 0; c < 4; c++) acc[s][c] = 0.f;
#pragma unroll
            for (int j = 0; j < 16; j += 4) {
#pragma unroll
                for (int s = 0; s < SCAN_NS; s++) {
                    float4 kk = *(const float4*)(pkp[s] + j);
                    float4 qq = *(const float4*)(pqp[s] + j);
                    s_loc[j + 0] += kk.x * vd[s]; acc[s][0] += qq.x * s_loc[j + 0];
                    s_loc[j + 1] += kk.y * vd[s]; acc[s][1] += qq.y * s_loc[j + 1];
                    s_loc[j + 2] += kk.z * vd[s]; acc[s][2] += qq.z * s_loc[j + 2];
                    s_loc[j + 3] += kk.w * vd[s]; acc[s][3] += qq.w * s_loc[j + 3];
                }
            }
#pragma unroll
            for (int s = 0; s < SCAN_NS; s++)
                s_red[s][tid] = (acc[s][0] + acc[s][1]) + (acc[s][2] + acc[s][3]);
        }

        {
            float qzp[SCAN_NS];
#pragma unroll
            for (int s = 0; s < SCAN_NS; s++) qzp[s] = 0.f;
            if (tid < 128) {
                float z = s_z[tid];
#pragma unroll
                for (int s = 0; s < SCAN_NS; s++) {
                    z += s_pk[buf][s][tid];
                    qzp[s] = s_pq[buf][s][tid] * z;
                }
                s_z[tid] = z;
            }
#pragma unroll
            for (int off = 16; off; off >>= 1) {
#pragma unroll
                for (int s = 0; s < SCAN_NS; s++)
                    qzp[s] += __shfl_xor_sync(0xffffffffu, qzp[s], off);
            }
            if (tid < 128 && (tid & 31) == 0) {
#pragma unroll
                for (int s = 0; s < SCAN_NS; s++) s_qzp[s][tid >> 5] = qzp[s];
            }
        }
        __syncthreads();

        if (tid < 32) {
#pragma unroll
            for (int stp = 0; stp < SCAN_NS; stp++) {
                const float* rd = s_red[stp];
                float qs = ((rd[dl] + rd[32 + dl]) + (rd[64 + dl] + rd[96 + dl])) +
                           ((rd[128 + dl] + rd[160 + dl]) + (rd[192 + dl] + rd[224 + dl]));
                float qz = (s_qzp[stp][0] + s_qzp[stp][1]) +
                           (s_qzp[stp][2] + s_qzp[stp][3]);
                qz = fmaxf(qz, EPS_RFA);
                attn[(t0 + stp) * v_stride + o_off + dl] = qs / qz;
            }
        }

        buf ^= 1;
        if (it + 1 < NGRP) {
            if (tid < 128) {
#pragma unroll
                for (int s = 0; s < SCAN_NS; s++) {
                    s_pq[buf][s][tid] = ld_pq[s];
                    s_pk[buf][s][tid] = ld_pk[s];
                }
            }
            if (tid < 32) {
#pragma unroll
                for (int s = 0; s < SCAN_NS; s++) s_v[buf][s][tid] = ld_v[s];
            }
        }
        __syncthreads();
    }
}

// ---------------------------------------------------------------------------
extern "C" void kernel_launch(void* const* d_in, const int* in_sizes, int n_in,
                              void* d_out, int out_size)
{
    const float* x  = (const float*)d_in[0];
    const float* rm = (const float*)d_in[1];
    const float* Wq = (const float*)d_in[2];
    const float* bq = (const float*)d_in[3];
    const float* Wk = (const float*)d_in[4];
    const float* bk = (const float*)d_in[5];
    const float* Wv = (const float*)d_in[6];
    const float* bv = (const float*)d_in[7];
    const float* Wo = (const float*)d_in[8];
    const float* bo = (const float*)d_in[9];
    float* out = (float*)d_out;

    __half *x_hi, *x_lo, *Wq_hi, *Wq_lo, *Wk_hi, *Wk_lo, *Wv_hi,
           *Wo_hi, *Wo_lo, *attn_hi;
    float *bq_eff, *bk_eff, *vbuf, *phiq, *phik, *attn_f32, *inv_s;
    cudaGetSymbolAddress((void**)&x_hi, g_x_hi);
    cudaGetSymbolAddress((void**)&x_lo, g_x_lo);
    cudaGetSymbolAddress((void**)&Wq_hi, g_Wq_hi);
    cudaGetSymbolAddress((void**)&Wq_lo, g_Wq_lo);
    cudaGetSymbolAddress((void**)&Wk_hi, g_Wk_hi);
    cudaGetSymbolAddress((void**)&Wk_lo, g_Wk_lo);
    cudaGetSymbolAddress((void**)&Wv_hi, g_Wv_hi);
    cudaGetSymbolAddress((void**)&Wo_hi, g_Wo_hi);
    cudaGetSymbolAddress((void**)&Wo_lo, g_Wo_lo);
    cudaGetSymbolAddress((void**)&attn_hi, g_attn_hi);
    cudaGetSymbolAddress((void**)&attn_f32, g_attn_f32);
    cudaGetSymbolAddress((void**)&inv_s, g_inv_s);
    cudaGetSymbolAddress((void**)&bq_eff, g_bq_eff);
    cudaGetSymbolAddress((void**)&bk_eff, g_bk_eff);
    cudaGetSymbolAddress((void**)&vbuf, g_v);
    cudaGetSymbolAddress((void**)&phiq, g_phiq);
    cudaGetSymbolAddress((void**)&phik, g_phik);

    cudaFuncSetAttribute((const void*)tc_gemm_phi,
                         cudaFuncAttributeMaxDynamicSharedMemorySize, SM4_TOTAL);
    cudaFuncSetAttribute((const void*)tc_gemm2<1>,
                         cudaFuncAttributeMaxDynamicSharedMemorySize, SM3_TOTAL);
    cudaFuncSetAttribute((const void*)tc_gemm2<2>,
                         cudaFuncAttributeMaxDynamicSharedMemorySize, SM3_TOTAL);

    // conversions + weight prep: x scaled x256, weights x64 (fp16 lo range).
    f32_to_f16hl<<<TB * E_DIM / 1024, 256>>>(x, x_hi, x_lo, TB * E_DIM, 256.0f);
    prep_weff<<<dim3(16, 16), 256>>>(rm, Wq, bq, Wq_hi, Wq_lo, bq_eff, 0.125f);
    prep_weff<<<dim3(16, 16), 256>>>(rm, Wk, bk, Wk_hi, Wk_lo, bk_eff, 1.0f);
    // Wv needs only hi (2-term drops B_lo); Wo needs hi+lo
    f32_to_f16hl<<<E_DIM * E_DIM / 1024, 256>>>(Wv, Wv_hi, nullptr, E_DIM * E_DIM, 64.0f);
    f32_to_f16hl<<<E_DIM * E_DIM / 1024, 256>>>(Wo, Wo_hi, Wo_lo, E_DIM * E_DIM, 64.0f);

    dim3 gg(E_DIM / BN, TB / BM);   // (8, 128)
    const float inv = 1.0f / 16384.0f;   // undo x256 * W64
    // phi GEMMs: fp16 3-term with RN drain (amplified path)
    tc_gemm_phi<<<gg, 256, SM4_TOTAL>>>(x_hi, x_lo, Wq_hi, Wq_lo, bq_eff, phiq, inv);
    tc_gemm_phi<<<gg, 256, SM4_TOTAL>>>(x_hi, x_lo, Wk_hi, Wk_lo, bk_eff, phik, inv);
    // v GEMM: 2-term drop B_lo, 3-stage, 2 CTAs/SM
    tc_gemm2<1><<<gg, 256, SM3_TOTAL>>>(x_hi, x_lo, Wv_hi, bv, vbuf, inv, nullptr);

    // causal scan -> fp32 attn
    rfa_scan<<<B_DIM * H_DIM * 2, 256>>>(phiq, phik, vbuf, attn_f32);

    // per-row scale -> fp16 attn_hi + inv_s
    rowscale<<<TB / 8, 256>>>(attn_f32, attn_hi, inv_s);

    // out GEMM: 2-term drop A_lo, 3-stage, 2 CTAs/SM; inv_s[row]/64
    tc_gemm2<2><<<gg, 256, SM3_TOTAL>>>(attn_hi, Wo_hi, Wo_lo, bo, out,
                                        1.0f / 64.0f, inv_s);
}